// round 13
// baseline (speedup 1.0000x reference)
#include <cuda_runtime.h>

#define Nn    100000
#define Ee    800000
#define INF   256
#define HIDD  64
#define HD    128
#define CC    40
#define EPSL  1e-5f
#define FULL  0xffffffffu
#define GBLK  1564
#define QKVB  782
#define EMAX  2560

// ---------------- scratch ----------------
__device__ float g_h[Nn * HIDD];
__device__ float g_prev[Nn * HIDD];
__device__ float g_vm[Nn * HIDD];
__device__ float g_rsq[Nn];
__device__ float g_kvs[2 * HIDD * HIDD];
__device__ float g_sumK[HD];
__device__ float g_sumV[HD];
__device__ float g_sums[2];
__device__ int   g_cnt[Nn];
__device__ int   g_ptr[Nn + 1];
__device__ int   g_cur[Nn];
__device__ int   g_erow[Ee];
__device__ int   g_blk[512];
__device__ unsigned g_hh[Nn * 32];
__device__ unsigned g_hl[Nn * 32];
__device__ unsigned g_qf[(size_t)GBLK * 4096];
__device__ unsigned g_kp[Nn * 64];
__device__ unsigned g_vp[Nn * 64];
__device__ unsigned g_kvsp[4608];
__device__ unsigned g_w0h[8192], g_w0l[8192];
__device__ unsigned g_wfh[24576], g_wfl[24576];

// ---------------- bf16 helpers ----------------
__device__ __forceinline__ unsigned packbf2(float f0, float f1) {
    unsigned r; asm("cvt.rn.bf16x2.f32 %0, %1, %2;" : "=r"(r) : "f"(f1), "f"(f0)); return r;
}
__device__ __forceinline__ void bsplit2(float f0, float f1, unsigned& h, unsigned& l) {
    h = packbf2(f0, f1);
    float h0 = __uint_as_float(h << 16);
    float h1 = __uint_as_float(h & 0xffff0000u);
    l = packbf2(f0 - h0, f1 - h1);
}
__device__ __forceinline__ void mma16(float* d, const unsigned* a, const unsigned* b) {
    asm volatile("mma.sync.aligned.m16n8k16.row.col.f32.bf16.bf16.f32 "
        "{%0,%1,%2,%3}, {%4,%5,%6,%7}, {%8,%9}, {%0,%1,%2,%3};"
        : "+f"(d[0]), "+f"(d[1]), "+f"(d[2]), "+f"(d[3])
        : "r"(a[0]), "r"(a[1]), "r"(a[2]), "r"(a[3]), "r"(b[0]), "r"(b[1]));
}

// frag position for A element pair: row r (0..63), pair p (0..31)
__device__ __forceinline__ int aFragPos(int r, int p) {
    return (((r >> 4) * 4 + (p >> 3)) * 32 + ((r & 7) * 4 + (p & 3))) * 4
           + ((r >> 3) & 1) + 2 * ((p >> 2) & 1);
}

// ---------------- weight pre-split ----------------
__global__ void k_prep(const float* __restrict__ fc0_w, const float* __restrict__ Wq,
                       const float* __restrict__ Wk, const float* __restrict__ Wv) {
    int id = blockIdx.x * 256 + threadIdx.x;
    if (id < 8192) {
        int kc = id >> 11, rem = id & 2047;
        int reg = rem & 1, lane = (rem >> 1) & 31, ntg = (rem >> 6) & 7, kt = rem >> 9;
        int t = lane & 3, gg = lane >> 2;
        int k = kc * 64 + kt * 16 + reg * 8 + 2 * t;
        int c = ntg * 8 + gg;
        float f0 = fc0_w[k * HIDD + c], f1 = fc0_w[(k + 1) * HIDD + c];
        unsigned h, l; bsplit2(f0, f1, h, l);
        g_w0h[id] = h; g_w0l[id] = l;
    } else if (id < 32768) {
        int id2 = id - 8192;
        int layer = id2 / 12288, r3 = id2 % 12288;
        int mat = r3 >> 12, cc2 = (r3 >> 11) & 1, rem = r3 & 2047;
        int reg = rem & 1, lane = (rem >> 1) & 31, ntg = (rem >> 6) & 7, kt = rem >> 9;
        int t = lane & 3, gg = lane >> 2;
        const float* W = (mat == 0 ? Wq : (mat == 1 ? Wk : Wv)) + (size_t)layer * HIDD * HD;
        int k = kt * 16 + reg * 8 + 2 * t;
        int cg = cc2 * 64 + ntg * 8 + gg;
        float f0 = W[k * HD + cg], f1 = W[(k + 1) * HD + cg];
        unsigned h, l; bsplit2(f0, f1, h, l);
        g_wfh[id2] = h; g_wfl[id2] = l;
    }
}

// ---------------- fc0: cp.async double-buffered x staging ----------------
// smem (uints): AH [0,8192) | AL [8192,16384) | raw 2x4096 floats [16384,24576)
__global__ void k_fc0(const float* __restrict__ x, const float* __restrict__ bias,
                      const float* __restrict__ lnw, const float* __restrict__ lnb) {
    extern __shared__ __align__(16) unsigned smf[];
    float* raw = (float*)&smf[16384];
    float* scr = (float*)smf;
    int tid = threadIdx.x, lane = tid & 31, warp = tid >> 5;
    int rw = warp & 3, cw = warp >> 2, g = lane >> 2, t = lane & 3;
    int row0 = blockIdx.x * 64;

    auto issue = [&](int kc) {
#pragma unroll
        for (int i = 0; i < 4; i++) {
            int idx = tid + i * 256;
            int r = idx >> 4, q4 = idx & 15;
            int gr = row0 + r;
            const float* src = &x[(size_t)(gr < Nn ? gr : 0) * INF + kc * 64 + q4 * 4];
            unsigned sa = (unsigned)__cvta_generic_to_shared(&raw[(kc & 1) * 4096 + idx * 4]);
            int sz = (gr < Nn) ? 16 : 0;
            asm volatile("cp.async.cg.shared.global [%0], [%1], 16, %2;"
                         :: "r"(sa), "l"(src), "r"(sz));
        }
        asm volatile("cp.async.commit_group;");
    };
    auto convert = [&](int kc) {
#pragma unroll
        for (int i = 0; i < 4; i++) {
            int idx = tid + i * 256;
            int r = idx >> 4, q4 = idx & 15;
            float4 v = *(const float4*)&raw[(kc & 1) * 4096 + idx * 4];
            unsigned h0, l0, h1, l1;
            bsplit2(v.x, v.y, h0, l0);
            bsplit2(v.z, v.w, h1, l1);
            int pos0 = kc * 2048 + aFragPos(r, q4 * 2);
            int pos1 = kc * 2048 + aFragPos(r, q4 * 2 + 1);
            smf[pos0] = h0; smf[8192 + pos0] = l0;
            smf[pos1] = h1; smf[8192 + pos1] = l1;
        }
    };

    issue(0); issue(1);
    asm volatile("cp.async.wait_group 1;"); convert(0); issue(2);
    asm volatile("cp.async.wait_group 1;"); convert(1); issue(3);
    asm volatile("cp.async.wait_group 1;"); convert(2);
    asm volatile("cp.async.wait_group 0;"); convert(3);
    __syncthreads();

    float acc[4][4] = {};
#pragma unroll
    for (int u = 0; u < 16; u++) {
        int kc = u >> 2, kt = u & 3;
        int abase = kc * 2048 + ((rw * 4 + kt) * 32 + lane) * 4;
        uint4 ah = *(const uint4*)&smf[abase];
        uint4 al = *(const uint4*)&smf[8192 + abase];
        const unsigned* wh = g_w0h + kc * 2048;
        const unsigned* wl = g_w0l + kc * 2048;
#pragma unroll
        for (int nt = 0; nt < 4; nt++) {
            int off = ((kt * 8 + cw * 4 + nt) * 32 + lane) * 2;
            uint2 bh = *(const uint2*)&wh[off];
            uint2 bl = *(const uint2*)&wl[off];
            mma16(acc[nt], (const unsigned*)&ah, (const unsigned*)&bh);
            mma16(acc[nt], (const unsigned*)&ah, (const unsigned*)&bl);
            mma16(acc[nt], (const unsigned*)&al, (const unsigned*)&bh);
        }
    }
    __syncthreads();
#pragma unroll
    for (int nt = 0; nt < 4; nt++) {
        int c0 = cw * 32 + nt * 8 + t * 2;
        float b0v = bias[c0], b1v = bias[c0 + 1];
        int r0 = rw * 16 + g, r1 = r0 + 8;
        scr[r0 * 68 + c0] = acc[nt][0] + b0v; scr[r0 * 68 + c0 + 1] = acc[nt][1] + b1v;
        scr[r1 * 68 + c0] = acc[nt][2] + b0v; scr[r1 * 68 + c0 + 1] = acc[nt][3] + b1v;
    }
    __syncthreads();
    int r = tid >> 2, sub = tid & 3;
    float vbuf[16];
    float s = 0.f, sq = 0.f;
#pragma unroll
    for (int j = 0; j < 16; j++) { float v = scr[r * 68 + sub * 16 + j]; vbuf[j] = v; s += v; sq += v * v; }
    s += __shfl_xor_sync(FULL, s, 1); sq += __shfl_xor_sync(FULL, sq, 1);
    s += __shfl_xor_sync(FULL, s, 2); sq += __shfl_xor_sync(FULL, sq, 2);
    float mu = s * 0.015625f;
    float var = sq * 0.015625f - mu * mu;
    float rs = rsqrtf(var + EPSL);
    int gr = row0 + r;
    if (gr < Nn) {
        float y[16];
#pragma unroll
        for (int j = 0; j < 16; j++) {
            int c = sub * 16 + j;
            float yy = (vbuf[j] - mu) * rs * lnw[c] + lnb[c];
            yy = fmaxf(yy, 0.f);
            y[j] = yy;
            g_prev[(size_t)gr * HIDD + c] = yy;
        }
#pragma unroll
        for (int jp = 0; jp < 8; jp++) {
            unsigned h, l; bsplit2(y[2 * jp], y[2 * jp + 1], h, l);
            g_hh[(size_t)gr * 32 + sub * 8 + jp] = h;
            g_hl[(size_t)gr * 32 + sub * 8 + jp] = l;
        }
    }
}

// ---------------- CSR build ----------------
__global__ void k_zcnt() { int i = blockIdx.x * 256 + threadIdx.x; if (i < Nn) g_cnt[i] = 0; }
__global__ void k_count(const int* __restrict__ col) {
    int e = blockIdx.x * 256 + threadIdx.x;
    if (e < Ee) atomicAdd(&g_cnt[col[e]], 1);
}
__global__ void k_rsqk() {
    int i = blockIdx.x * 256 + threadIdx.x;
    if (i < Nn) { int c = g_cnt[i]; g_rsq[i] = c > 0 ? rsqrtf((float)c) : 0.f; }
}
__device__ __forceinline__ int blockScanIncl(int val, int* wsum) {
    int lane = threadIdx.x & 31, wid = threadIdx.x >> 5;
#pragma unroll
    for (int o = 1; o < 32; o <<= 1) {
        int n = __shfl_up_sync(FULL, val, o);
        if (lane >= o) val += n;
    }
    if (lane == 31) wsum[wid] = val;
    __syncthreads();
    if (wid == 0) {
        int nw = blockDim.x >> 5;
        int w = (lane < nw) ? wsum[lane] : 0;
#pragma unroll
        for (int o = 1; o < 32; o <<= 1) {
            int n = __shfl_up_sync(FULL, w, o);
            if (lane >= o) w += n;
        }
        wsum[lane] = w;
    }
    __syncthreads();
    return val + (wid > 0 ? wsum[wid - 1] : 0);
}
__global__ void k_scan1() {
    __shared__ int wsum[32];
    int i = blockIdx.x * 256 + threadIdx.x;
    int v = (i < Nn) ? g_cnt[i] : 0;
    int incl = blockScanIncl(v, wsum);
    if (i < Nn) g_ptr[i] = incl - v;
    if (threadIdx.x == 255) g_blk[blockIdx.x] = incl;
}
__global__ void k_scan2() {
    __shared__ int wsum[32];
    const int NB = (Nn + 255) / 256;
    int v = (threadIdx.x < NB) ? g_blk[threadIdx.x] : 0;
    int incl = blockScanIncl(v, wsum);
    if (threadIdx.x < NB) g_blk[threadIdx.x] = incl - v;
}
__global__ void k_scan3() {
    int i = blockIdx.x * 256 + threadIdx.x;
    if (i < Nn) {
        int p = g_ptr[i] + g_blk[i >> 8];
        g_ptr[i] = p; g_cur[i] = p;
    }
    if (i == 0) g_ptr[Nn] = Ee;
}
__global__ void k_fill(const int* __restrict__ row, const int* __restrict__ col) {
    int e = blockIdx.x * 256 + threadIdx.x;
    if (e < Ee) {
        int c = col[e];
        int p = atomicAdd(&g_cur[c], 1);
        g_erow[p] = row[e];
    }
}

// ---------------- per-layer reduction zero ----------------
__global__ void k_zero_red() {
    int i = blockIdx.x * blockDim.x + threadIdx.x;
    int stride = gridDim.x * blockDim.x;
    for (int j = i; j < 8192; j += stride) g_kvs[j] = 0.f;
    if (i < HD) { g_sumK[i] = 0.f; g_sumV[i] = 0.f; }
    if (i < 2) g_sums[i] = 0.f;
}

// ---------------- QKV: 128-row tiles, B from global, packed epilogues ----------------
__global__ __launch_bounds__(256, 2) void k_qkv(int layer, const float* __restrict__ bq,
                      const float* __restrict__ bk, const float* __restrict__ bv) {
    extern __shared__ __align__(16) unsigned smd[];   // AH 4096 | AL 4096 | E 4608
    unsigned* E = &smd[8192];
    float* Ef = (float*)E;
    __shared__ float sK[128], sV[128];
    int tid = threadIdx.x, lane = tid & 31, warp = tid >> 5;
    int rw = warp & 3, cw = warp >> 2, g = lane >> 2, t = lane & 3;
    int row0 = blockIdx.x * 128;
    const unsigned* wfh = g_wfh + layer * 12288;
    const unsigned* wfl = g_wfl + layer * 12288;
    if (tid < 128) { sK[tid] = 0.f; sV[tid] = 0.f; }
#pragma unroll
    for (int i = 0; i < 16; i++) {
        int idx = tid + i * 256;
        int r = idx >> 5, p = idx & 31;
        int gr = row0 + r;
        unsigned hv = 0, lv = 0;
        if (gr < Nn) { hv = g_hh[(size_t)gr * 32 + p]; lv = g_hl[(size_t)gr * 32 + p]; }
        int pos = (r >> 6) * 2048 + aFragPos(r & 63, p);
        smd[pos] = hv; smd[4096 + pos] = lv;
    }
    __syncthreads();
    bool rok[2][2];
#pragma unroll
    for (int tl = 0; tl < 2; tl++) {
        rok[tl][0] = (row0 + tl * 64 + rw * 16 + g) < Nn;
        rok[tl][1] = (row0 + tl * 64 + rw * 16 + g + 8) < Nn;
    }
    float q2 = 0.f, k2 = 0.f;
    float vk0[2][4][4];
#pragma unroll
    for (int ch = 0; ch < 6; ch++) {
        int mat = ch >> 1, cc2 = ch & 1;
        const float* B = mat == 0 ? bq : (mat == 1 ? bk : bv);
        bool split = (mat == 2);
        const unsigned* wh = wfh + ch * 2048;
        const unsigned* wl = wfl + ch * 2048;
        float acc[2][4][4] = {};
#pragma unroll
        for (int kt = 0; kt < 4; kt++) {
            uint4 ah0 = *(uint4*)&smd[((rw * 4 + kt) * 32 + lane) * 4];
            uint4 ah1 = *(uint4*)&smd[2048 + ((rw * 4 + kt) * 32 + lane) * 4];
            uint4 al0, al1;
            if (split) {
                al0 = *(uint4*)&smd[4096 + ((rw * 4 + kt) * 32 + lane) * 4];
                al1 = *(uint4*)&smd[6144 + ((rw * 4 + kt) * 32 + lane) * 4];
            }
#pragma unroll
            for (int nt = 0; nt < 4; nt++) {
                int off = ((kt * 8 + cw * 4 + nt) * 32 + lane) * 2;
                uint2 bh = *(const uint2*)&wh[off];
                mma16(acc[0][nt], (const unsigned*)&ah0, (const unsigned*)&bh);
                mma16(acc[1][nt], (const unsigned*)&ah1, (const unsigned*)&bh);
                if (split) {
                    uint2 bl = *(const uint2*)&wl[off];
                    mma16(acc[0][nt], (const unsigned*)&ah0, (const unsigned*)&bl);
                    mma16(acc[0][nt], (const unsigned*)&al0, (const unsigned*)&bh);
                    mma16(acc[1][nt], (const unsigned*)&ah1, (const unsigned*)&bl);
                    mma16(acc[1][nt], (const unsigned*)&al1, (const unsigned*)&bh);
                }
            }
        }
#pragma unroll
        for (int nt = 0; nt < 4; nt++) {
            int cgl = cc2 * 64 + cw * 32 + nt * 8 + t * 2;
            float b0v = B[cgl], b1v = B[cgl + 1];
            float c0s = 0.f, c1s = 0.f;
#pragma unroll
            for (int tl = 0; tl < 2; tl++) {
                acc[tl][nt][0] += b0v; acc[tl][nt][1] += b1v;
                acc[tl][nt][2] += b0v; acc[tl][nt][3] += b1v;
                float v00 = rok[tl][0] ? acc[tl][nt][0] : 0.f;
                float v01 = rok[tl][0] ? acc[tl][nt][1] : 0.f;
                float v10 = rok[tl][1] ? acc[tl][nt][2] : 0.f;
                float v11 = rok[tl][1] ? acc[tl][nt][3] : 0.f;
                if (mat == 0)      q2 += v00 * v00 + v01 * v01 + v10 * v10 + v11 * v11;
                else if (mat == 1) k2 += v00 * v00 + v01 * v01 + v10 * v10 + v11 * v11;
                if (mat >= 1) { c0s += v00 + v10; c1s += v01 + v11; }
            }
            if (mat >= 1) {
                c0s += __shfl_xor_sync(FULL, c0s, 4);  c1s += __shfl_xor_sync(FULL, c1s, 4);
                c0s += __shfl_xor_sync(FULL, c0s, 8);  c1s += __shfl_xor_sync(FULL, c1s, 8);
                c0s += __shfl_xor_sync(FULL, c0s, 16); c1s += __shfl_xor_sync(FULL, c1s, 16);
                if (g == 0) {
                    float* sd = (mat == 1) ? sK : sV;
                    atomicAdd(&sd[cgl], c0s);
                    atomicAdd(&sd[cgl + 1], c1s);
                }
            }
        }
        int r0 = rw * 16 + g, r1 = r0 + 8;
        if (mat == 0) {
            __syncthreads();
#pragma unroll
            for (int tl = 0; tl < 2; tl++)
#pragma unroll
                for (int nt = 0; nt < 4; nt++) {
                    int p = cw * 16 + nt * 4 + t;
                    E[tl * 2048 + aFragPos(r0, p)] = packbf2(acc[tl][nt][0], acc[tl][nt][1]);
                    E[tl * 2048 + aFragPos(r1, p)] = packbf2(acc[tl][nt][2], acc[tl][nt][3]);
                }
            __syncthreads();
#pragma unroll
            for (int i = 0; i < 4; i++) {
                int u = (tid + i * 256) * 4;
                int tile = u >> 11, w = u & 2047;
                *(uint4*)&g_qf[(size_t)(blockIdx.x * 2 + tile) * 4096 + cc2 * 2048 + w] =
                    *(uint4*)&E[u];
            }
        } else {
            unsigned* dst = (mat == 1) ? g_kp : g_vp;
#pragma unroll
            for (int tl = 0; tl < 2; tl++) {
                __syncthreads();
#pragma unroll
                for (int nt = 0; nt < 4; nt++) {
                    int p = cw * 16 + nt * 4 + t;
                    E[r0 * 36 + p] = packbf2(acc[tl][nt][0], acc[tl][nt][1]);
                    E[r1 * 36 + p] = packbf2(acc[tl][nt][2], acc[tl][nt][3]);
                }
                __syncthreads();
#pragma unroll
                for (int i = 0; i < 2; i++) {
                    int idx4 = tid + i * 256;
                    int r = idx4 >> 3, p4 = idx4 & 7;
                    int gr = row0 + tl * 64 + r;
                    if (gr < Nn)
                        *(uint4*)&dst[(size_t)gr * 64 + cc2 * 32 + p4 * 4] =
                            *(uint4*)&E[r * 36 + p4 * 4];
                }
            }
            if (mat == 2) {
                if (cc2 == 0) {
#pragma unroll
                    for (int tl = 0; tl < 2; tl++)
#pragma unroll
                        for (int nt = 0; nt < 4; nt++)
#pragma unroll
                            for (int j = 0; j < 4; j++) vk0[tl][nt][j] = acc[tl][nt][j];
                } else {
#pragma unroll
                    for (int tl = 0; tl < 2; tl++) {
                        __syncthreads();
#pragma unroll
                        for (int nt = 0; nt < 4; nt++) {
                            int c0 = cw * 32 + nt * 8 + 2 * t;
                            Ef[r0 * 72 + c0]     = 0.5f * (vk0[tl][nt][0] + acc[tl][nt][0]);
                            Ef[r0 * 72 + c0 + 1] = 0.5f * (vk0[tl][nt][1] + acc[tl][nt][1]);
                            Ef[r1 * 72 + c0]     = 0.5f * (vk0[tl][nt][2] + acc[tl][nt][2]);
                            Ef[r1 * 72 + c0 + 1] = 0.5f * (vk0[tl][nt][3] + acc[tl][nt][3]);
                        }
                        __syncthreads();
#pragma unroll
                        for (int i = 0; i < 4; i++) {
                            int idx = tid + i * 256;
                            int r = idx >> 4, c4 = idx & 15;
                            int gr = row0 + tl * 64 + r;
                            if (gr < Nn)
                                *(float4*)&g_vm[(size_t)gr * 64 + c4 * 4] =
                                    *(float4*)&Ef[r * 72 + c4 * 4];
                        }
                    }
                }
            }
        }
    }
#pragma unroll
    for (int o = 16; o > 0; o >>= 1) {
        q2 += __shfl_xor_sync(FULL, q2, o);
        k2 += __shfl_xor_sync(FULL, k2, o);
    }
    if (lane == 0) { atomicAdd(&g_sums[0], q2); atomicAdd(&g_sums[1], k2); }
    __syncthreads();
    if (tid < 128) { atomicAdd(&g_sumK[tid], sK[tid]); atomicAdd(&g_sumV[tid], sV[tid]); }
}

// ---------------- kvs = k^T v : packed bf16 inputs ----------------
__global__ void k_reduce() {
    __shared__ __align__(16) unsigned kraw[2048];
    __shared__ __align__(16) unsigned uraw[2048];
    __shared__ __align__(16) unsigned afr[2048];
    __shared__ __align__(16) unsigned bfr[2048];
    int tid = threadIdx.x, lane = tid & 31, warp = tid >> 5;
    int h = warp >> 2, mt = warp & 3;
    int t = lane & 3, g = lane >> 2;
    float acc[8][4] = {};
    const int NT = Nn / 32;
    for (int tt = blockIdx.x; tt < NT; tt += gridDim.x) {
        __syncthreads();
#pragma unroll
        for (int i = 0; i < 2; i++) {
            int idx4 = tid + i * 256;
            int n = idx4 >> 4, p4 = idx4 & 15;
            *(uint4*)&kraw[n * 64 + p4 * 4] =
                *(const uint4*)&g_kp[(size_t)(tt * 32 + n) * 64 + p4 * 4];
            *(uint4*)&uraw[n * 64 + p4 * 4] =
                *(const uint4*)&g_vp[(size_t)(tt * 32 + n) * 64 + p4 * 4];
        }
        __syncthreads();
#pragma unroll
        for (int i = 0; i < 8; i++) {
            int idx = tid + i * 256;
            int j = idx & 3, ln = (idx >> 2) & 31, mtt = (idx >> 7) & 3,
                ks = (idx >> 9) & 1, hh = (idx >> 10) & 1;
            int lt = ln & 3, lg = ln >> 2;
            int m = mtt * 16 + lg + (j & 1) * 8;
            int n0 = ks * 16 + 2 * lt + (j >> 1) * 8;
            int hm = hh * 64 + m;
            unsigned u0 = kraw[n0 * 64 + (hm >> 1)];
            unsigned u1 = kraw[(n0 + 1) * 64 + (hm >> 1)];
            afr[idx] = __byte_perm(u0, u1, (hm & 1) ? 0x7632 : 0x5410);
        }
#pragma unroll
        for (int i = 0; i < 8; i++) {
            int idx = tid + i * 256;
            int reg = idx & 1, ln = (idx >> 1) & 31, ntg = (idx >> 6) & 7,
                ks = (idx >> 9) & 1, hh = (idx >> 10) & 1;
            int lt = ln & 3, lg = ln >> 2;
            int hd = hh * 64 + ntg * 8 + lg;
            int n0 = ks * 16 + 2 * lt + reg * 8;
            unsigned u0 = uraw[n0 * 64 + (hd >> 1)];
            unsigned u1 = uraw[(n0 + 1) * 64 + (hd >> 1)];
            bfr[idx] = __byte_perm(u0, u1, (hd & 1) ? 0x7632 : 0x5410);
        }
        __syncthreads();
#pragma unroll
        for (int ks = 0; ks < 2; ks++) {
            uint4 a = *(uint4*)&afr[((h * 2 + ks) * 4 + mt) * 128 + lane * 4];
#pragma unroll
            for (int nt = 0; nt < 8; nt++) {
                uint2 b = *(uint2*)&bfr[(((h * 2 + ks) * 8 + nt) * 32 + lane) * 2];
                mma16(acc[nt], (const unsigned*)&a, (const unsigned*)&b);
            }
        }
    }
#pragma unroll
    for (int nt = 0; nt < 8; nt++) {
        int c0 = nt * 8 + 2 * t;
        int r0 = mt * 16 + g, r1 = r0 + 8;
        atomicAdd(&g_kvs[h * 4096 + r0 * 64 + c0],     acc[nt][0]);
        atomicAdd(&g_kvs[h * 4096 + r0 * 64 + c0 + 1], acc[nt][1]);
        atomicAdd(&g_kvs[h * 4096 + r1 * 64 + c0],     acc[nt][2]);
        atomicAdd(&g_kvs[h * 4096 + r1 * 64 + c0 + 1], acc[nt][3]);
    }
}

// ---------------- pack kvs (+ sumK as col 64) into B-fragment order ----------------
__global__ void k_pkvs() {
    int gid = blockIdx.x * 256 + threadIdx.x;
    if (gid >= 4608) return;
    int h = gid / 2304, rem = gid % 2304;
    int reg = rem & 1, ln = (rem >> 1) & 31, ntg = (rem >> 6) % 9, kt = rem / 576;
    int lt = ln & 3, lg = ln >> 2;
    int m = kt * 16 + reg * 8 + 2 * lt;
    unsigned val;
    if (ntg < 8) {
        int c = ntg * 8 + lg;
        val = packbf2(g_kvs[h * 4096 + m * 64 + c], g_kvs[h * 4096 + (m + 1) * 64 + c]);
    } else {
        val = (lg == 0) ? packbf2(g_sumK[h * 64 + m], g_sumK[h * 64 + m + 1]) : 0u;
    }
    g_kvsp[gid] = val;
}

// ---------------- fused attention + GCN gather (smem-staged edges) + LN ----------------
__global__ void k_attnc(const float* __restrict__ lnw, const float* __restrict__ lnb) {
    __shared__ float scrf[64 * 68];
    __shared__ float sVs[128];
    __shared__ float denS[128];
    __shared__ int   sE[EMAX];
    __shared__ float sWt[EMAX];
    int tid = threadIdx.x, lane = tid & 31, warp = tid >> 5;
    int rw = warp & 3, cw = warp >> 2, g = lane >> 2, t = lane & 3;
    int row0 = blockIdx.x * 64;
    int e0 = g_ptr[row0];
    int rend = (row0 + 64 < Nn) ? row0 + 64 : Nn;
    int nE = g_ptr[rend] - e0;
    bool staged = (nE <= EMAX);
    if (staged) {
        for (int i = tid; i < nE; i += 256) {
            int rr = g_erow[e0 + i];
            sE[i] = rr;
            sWt[i] = g_rsq[rr];
        }
    }
    float sc = rsqrtf(g_sums[0] * g_sums[1]);
    if (tid < 128) sVs[tid] = g_sumV[tid];
    float acc0[5][4] = {}, acc1[5][4] = {};
    int ntn = 4 + cw;
#pragma unroll
    for (int kt = 0; kt < 4; kt++) {
        uint4 a = *(const uint4*)&g_qf[(size_t)blockIdx.x * 4096 + ((rw * 4 + kt) * 32 + lane) * 4];
#pragma unroll
        for (int nt = 0; nt < 5; nt++) {
            if (nt < ntn) {
                int ntg = cw * 4 + nt;
                uint2 b = *(const uint2*)&g_kvsp[((kt * 9 + ntg) * 32 + lane) * 2];
                mma16(acc0[nt], (const unsigned*)&a, (const unsigned*)&b);
            }
        }
    }
#pragma unroll
    for (int kt = 0; kt < 4; kt++) {
        uint4 a = *(const uint4*)&g_qf[(size_t)blockIdx.x * 4096 + 2048 + ((rw * 4 + kt) * 32 + lane) * 4];
#pragma unroll
        for (int nt = 0; nt < 5; nt++) {
            if (nt < ntn) {
                int ntg = cw * 4 + nt;
                uint2 b = *(const uint2*)&g_kvsp[2304 + ((kt * 9 + ntg) * 32 + lane) * 2];
                mma16(acc1[nt], (const unsigned*)&a, (const unsigned*)&b);
            }
        }
    }
    if (cw == 1 && t == 0) {
        int r0 = rw * 16 + g;
        denS[r0]          = acc0[4][0] * sc + (float)Nn;
        denS[r0 + 8]      = acc0[4][2] * sc + (float)Nn;
        denS[64 + r0]     = acc1[4][0] * sc + (float)Nn;
        denS[64 + r0 + 8] = acc1[4][2] * sc + (float)Nn;
    }
    __syncthreads();
#pragma unroll
    for (int nt = 0; nt < 4; nt++) {
        int c = cw * 32 + nt * 8 + 2 * t;
        int r0 = rw * 16 + g, r1 = r0 + 8;
        float d00 = denS[r0], d01 = denS[r1];
        float d10 = denS[64 + r0], d11 = denS[64 + r1];
        scrf[r0 * 68 + c]     = 0.5f * ((acc0[nt][0] * sc + sVs[c])     / d00 + (acc1[nt][0] * sc + sVs[64 + c])     / d10);
        scrf[r0 * 68 + c + 1] = 0.5f * ((acc0[nt][1] * sc + sVs[c + 1]) / d00 + (acc1[nt][1] * sc + sVs[64 + c + 1]) / d10);
        scrf[r1 * 68 + c]     = 0.5f * ((acc0[nt][2] * sc + sVs[c])     / d01 + (acc1[nt][2] * sc + sVs[64 + c])     / d11);
        scrf[r1 * 68 + c + 1] = 0.5f * ((acc0[nt][3] * sc + sVs[c + 1]) / d01 + (acc1[nt][3] * sc + sVs[64 + c + 1]) / d11);
    }
    __syncthreads();
    int half = lane >> 4, hl = lane & 15;
#pragma unroll
    for (int pass = 0; pass < 4; pass++) {
        int nl = pass * 16 + warp * 2 + half;
        int n = row0 + nl;
        if (n < Nn) {
            int p0 = g_ptr[n], p1 = g_ptr[n + 1];
            float rn = g_rsq[n];
            float ax = 0.f, ay = 0.f, az = 0.f, aw = 0.f;
            if (staged) {
                int q = p0 - e0, q1 = p1 - e0;
                for (; q + 4 <= q1; q += 4) {
                    int r0 = sE[q], r1 = sE[q + 1], r2 = sE[q + 2], r3 = sE[q + 3];
                    float w0 = rn * sWt[q],     w1 = rn * sWt[q + 1];
                    float w2 = rn * sWt[q + 2], w3 = rn * sWt[q + 3];
                    float4 va = *(const float4*)&g_vm[(size_t)r0 * 64 + hl * 4];
                    float4 vb = *(const float4*)&g_vm[(size_t)r1 * 64 + hl * 4];
                    float4 vc = *(const float4*)&g_vm[(size_t)r2 * 64 + hl * 4];
                    float4 vd = *(const float4*)&g_vm[(size_t)r3 * 64 + hl * 4];
                    ax += w0 * va.x + w1 * vb.x + w2 * vc.x + w3 * vd.x;
                    ay += w0 * va.y + w1 * vb.y + w2 * vc.y + w3 * vd.y;
                    az += w0 * va.z + w1 * vb.z + w2 * vc.z + w3 * vd.z;
                    aw += w0 * va.w + w1 * vb.w + w2 * vc.w + w3 * vd.w;
                }
                for (; q < q1; q++) {
                    int r0 = sE[q];
                    float w0 = rn * sWt[q];
                    float4 va = *(const float4*)&g_vm[(size_t)r0 * 64 + hl * 4];
                    ax += w0 * va.x; ay += w0 * va.y; az += w0 * va.z; aw += w0 * va.w;
                }
            } else {
                for (int e = p0; e < p1; e++) {
                    int r0 = g_erow[e];
                    float w0 = rn * g_rsq[r0];
                    float4 va = *(const float4*)&g_vm[(size_t)r0 * 64 + hl * 4];
                    ax += w0 * va.x; ay += w0 * va.y; az += w0 * va.z; aw += w0 * va.w;
                }
            }
            float4 ov = *(const float4*)&scrf[nl * 68 + hl * 4];
            float4 pv = *(const float4*)&g_prev[(size_t)n * HIDD + hl * 4];
            float4 hv;
            hv.x = 0.5f * (ov.x + ax) + 0.5f * pv.x;
            hv.y = 0.5f * (ov.y + ay) + 0.5f * pv.y;
            hv.z = 0.5f * (ov.z + az) + 0.5f * pv.z;
            hv.w = 0.5f * (ov.w + aw) + 0.5f * pv.w;
            float s = hv.x + hv.y + hv.z + hv.w;
            float sq = hv.x * hv.x + hv.y * hv.y + hv.z * hv.z + hv.w * hv.w;
#pragma unroll
            for (int o = 1; o < 16; o <<= 1) {
                s += __shfl_xor_sync(FULL, s, o);
                sq += __shfl_xor_sync(FULL, sq, o);
            }
            float mu = s * 0.015625f;
            float var = sq * 0.015625f - mu * mu;
            float rs = rsqrtf(var + EPSL);
            float4 lw = *(const float4*)&lnw[hl * 4];
            float4 lb = *(const float4*)&lnb[hl * 4];
            float4 y;
            y.x = (hv.x - mu) * rs * lw.x + lb.x;
            y.y = (hv.y - mu) * rs * lw.y + lb.y;
            y.z = (hv.z - mu) * rs * lw.z + lb.z;
            y.w = (hv.w - mu) * rs * lw.w + lb.w;
            *(float4*)&g_h[(size_t)n * HIDD + hl * 4] = y;
            *(float4*)&g_prev[(size_t)n * HIDD + hl * 4] = y;
            unsigned h0, l0, h1, l1;
            bsplit2(y.x, y.y, h0, l0);
            bsplit2(y.z, y.w, h1, l1);
            *(uint2*)&g_hh[(size_t)n * 32 + hl * 2] = make_uint2(h0, h1);
            *(uint2*)&g_hl[(size_t)n * 32 + hl * 2] = make_uint2(l0, l1);
        }
    }
}

// ---------------- final projection ----------------
__global__ void k_fco(const float* __restrict__ w, const float* __restrict__ b,
                      float* __restrict__ out) {
    __shared__ float ws[64][40];
    __shared__ float hs[64][65];
    int tid = threadIdx.x;
    int row0 = blockIdx.x * 64;
    for (int l = tid; l < 64 * 40; l += 256) ws[l / 40][l % 40] = w[l];
#pragma unroll
    for (int l = 0; l < 4; l++) {
        int lin = tid + l * 256;
        int r = lin >> 4, c4 = lin & 15;
        int gr = row0 + r; if (gr >= Nn) gr = Nn - 1;
        float4 v = *(const float4*)&g_h[(size_t)gr * HIDD + c4 * 4];
        hs[r][c4 * 4 + 0] = v.x; hs[r][c4 * 4 + 1] = v.y;
        hs[r][c4 * 4 + 2] = v.z; hs[r][c4 * 4 + 3] = v.w;
    }
    __syncthreads();
    int r = tid & 63, cg = tid >> 6;
    float acc[10] = {};
#pragma unroll
    for (int kk = 0; kk < 64; kk++) {
        float a = hs[r][kk];
        const float* wr = &ws[kk][cg * 10];
#pragma unroll
        for (int j = 0; j < 10; j++) acc[j] += a * wr[j];
    }
    int gr = row0 + r;
    if (gr < Nn) {
#pragma unroll
        for (int j = 0; j < 10; j++)
            out[(size_t)gr * CC + cg * 10 + j] = acc[j] + b[cg * 10 + j];
    }
}

// ---------------- launcher ----------------
extern "C" void kernel_launch(void* const* d_in, const int* in_sizes, int n_in,
                              void* d_out, int out_size) {
    (void)in_sizes; (void)n_in; (void)out_size;
    const float* x     = (const float*)d_in[0];
    const int*   ei    = (const int*)d_in[1];
    const float* fc0_w = (const float*)d_in[2];
    const float* fc0_b = (const float*)d_in[3];
    const float* ln_w  = (const float*)d_in[4];
    const float* ln_b  = (const float*)d_in[5];
    const float* Wq    = (const float*)d_in[6];
    const float* Wk    = (const float*)d_in[7];
    const float* Wv    = (const float*)d_in[8];
    const float* bq    = (const float*)d_in[9];
    const float* bk    = (const float*)d_in[10];
    const float* bv    = (const float*)d_in[11];
    const float* fco_w = (const float*)d_in[12];
    const float* fco_b = (const float*)d_in[13];
    float* out = (float*)d_out;

    const int GB = 1563;
    const int NB = (Nn + 255) / 256;
    const int EB = (Ee + 255) / 256;
    const int QSM = 51200;
    const int FSM = 98304;   // frag 64KB + raw 32KB

    cudaFuncSetAttribute(k_qkv, cudaFuncAttributeMaxDynamicSharedMemorySize, QSM);
    cudaFuncSetAttribute(k_fc0, cudaFuncAttributeMaxDynamicSharedMemorySize, FSM);

    k_prep<<<128, 256>>>(fc0_w, Wq, Wk, Wv);                   // 1
    k_zcnt<<<NB, 256>>>();                                     // 2
    k_zero_red<<<34, 256>>>();                                 // 3
    k_fc0<<<GB, 256, FSM>>>(x, fc0_b, ln_w, ln_b);             // 4  <- profile slot
    k_qkv<<<QKVB, 256, QSM>>>(0, bq, bk, bv);                  // 5
    k_count<<<EB, 256>>>(ei + Ee);                             // 6
    k_rsqk<<<NB, 256>>>();                                     // 7
    k_scan1<<<NB, 256>>>();                                    // 8
    k_scan2<<<1, 512>>>();                                     // 9
    k_scan3<<<NB, 256>>>();                                    // 10
    k_fill<<<EB, 256>>>(ei, ei + Ee);                          // 11
    k_reduce<<<320, 256>>>();                                  // 12
    k_pkvs<<<18, 256>>>();                                     // 13
    k_attnc<<<GB, 256>>>(ln_w + HIDD, ln_b + HIDD);            // 14
    k_zero_red<<<34, 256>>>();                                 // 15
    k_qkv<<<QKVB, 256, QSM>>>(1, bq + HD, bk + HD, bv + HD);   // 16
    k_reduce<<<320, 256>>>();                                  // 17
    k_pkvs<<<18, 256>>>();                                     // 18
    k_attnc<<<GB, 256>>>(ln_w + 2 * HIDD, ln_b + 2 * HIDD);    // 19
    k_fco<<<GB, 256>>>(fco_w, fco_b, out);                     // 20
}

// round 14
// speedup vs baseline: 1.0432x; 1.0432x over previous
#include <cuda_runtime.h>

#define Nn    100000
#define Ee    800000
#define INF   256
#define HIDD  64
#define HD    128
#define CC    40
#define EPSL  1e-5f
#define FULL  0xffffffffu
#define GBLK  1564
#define QKVB  782
#define EMAX  2560

// ---------------- scratch ----------------
__device__ float g_h[Nn * HIDD];
__device__ float g_prev[Nn * HIDD];
__device__ float g_vm[Nn * HIDD];
__device__ float g_rsq[Nn];
__device__ float g_kvs[2 * HIDD * HIDD];
__device__ float g_sumK[HD];
__device__ float g_sumV[HD];
__device__ float g_sums[2];
__device__ int   g_cnt[Nn];
__device__ int   g_ptr[Nn + 1];
__device__ int   g_cur[Nn];
__device__ int   g_erow[Ee];
__device__ int   g_blk[512];
__device__ unsigned g_hh[Nn * 32];
__device__ unsigned g_hl[Nn * 32];
__device__ unsigned g_qf[(size_t)GBLK * 4096];
__device__ unsigned g_kp[Nn * 64];
__device__ unsigned g_vp[Nn * 64];
__device__ unsigned g_kvsp[4608];
__device__ unsigned g_w0h[8192], g_w0l[8192];
__device__ unsigned g_wfh[24576], g_wfl[24576];

// ---------------- bf16 helpers ----------------
__device__ __forceinline__ unsigned packbf2(float f0, float f1) {
    unsigned r; asm("cvt.rn.bf16x2.f32 %0, %1, %2;" : "=r"(r) : "f"(f1), "f"(f0)); return r;
}
__device__ __forceinline__ void bsplit2(float f0, float f1, unsigned& h, unsigned& l) {
    h = packbf2(f0, f1);
    float h0 = __uint_as_float(h << 16);
    float h1 = __uint_as_float(h & 0xffff0000u);
    l = packbf2(f0 - h0, f1 - h1);
}
__device__ __forceinline__ void mma16(float* d, const unsigned* a, const unsigned* b) {
    asm volatile("mma.sync.aligned.m16n8k16.row.col.f32.bf16.bf16.f32 "
        "{%0,%1,%2,%3}, {%4,%5,%6,%7}, {%8,%9}, {%0,%1,%2,%3};"
        : "+f"(d[0]), "+f"(d[1]), "+f"(d[2]), "+f"(d[3])
        : "r"(a[0]), "r"(a[1]), "r"(a[2]), "r"(a[3]), "r"(b[0]), "r"(b[1]));
}

// frag position for A element pair: row r (0..63), pair p (0..31)
__device__ __forceinline__ int aFragPos(int r, int p) {
    return (((r >> 4) * 4 + (p >> 3)) * 32 + ((r & 7) * 4 + (p & 3))) * 4
           + ((r >> 3) & 1) + 2 * ((p >> 2) & 1);
}

// ---------------- weight pre-split ----------------
__global__ void k_prep(const float* __restrict__ fc0_w, const float* __restrict__ Wq,
                       const float* __restrict__ Wk, const float* __restrict__ Wv) {
    int id = blockIdx.x * 256 + threadIdx.x;
    if (id < 8192) {
        int kc = id >> 11, rem = id & 2047;
        int reg = rem & 1, lane = (rem >> 1) & 31, ntg = (rem >> 6) & 7, kt = rem >> 9;
        int t = lane & 3, gg = lane >> 2;
        int k = kc * 64 + kt * 16 + reg * 8 + 2 * t;
        int c = ntg * 8 + gg;
        float f0 = fc0_w[k * HIDD + c], f1 = fc0_w[(k + 1) * HIDD + c];
        unsigned h, l; bsplit2(f0, f1, h, l);
        g_w0h[id] = h; g_w0l[id] = l;
    } else if (id < 32768) {
        int id2 = id - 8192;
        int layer = id2 / 12288, r3 = id2 % 12288;
        int mat = r3 >> 12, cc2 = (r3 >> 11) & 1, rem = r3 & 2047;
        int reg = rem & 1, lane = (rem >> 1) & 31, ntg = (rem >> 6) & 7, kt = rem >> 9;
        int t = lane & 3, gg = lane >> 2;
        const float* W = (mat == 0 ? Wq : (mat == 1 ? Wk : Wv)) + (size_t)layer * HIDD * HD;
        int k = kt * 16 + reg * 8 + 2 * t;
        int cg = cc2 * 64 + ntg * 8 + gg;
        float f0 = W[k * HD + cg], f1 = W[(k + 1) * HD + cg];
        unsigned h, l; bsplit2(f0, f1, h, l);
        g_wfh[id2] = h; g_wfl[id2] = l;
    }
}

// ---------------- fc0: all-A-upfront, ONE sync, barrier-free mainloop (R12 best) ----------------
__global__ void k_fc0(const float* __restrict__ x, const float* __restrict__ bias,
                      const float* __restrict__ lnw, const float* __restrict__ lnb) {
    extern __shared__ __align__(16) unsigned smf[];
    float* scr = (float*)smf;
    int tid = threadIdx.x, lane = tid & 31, warp = tid >> 5;
    int rw = warp & 3, cw = warp >> 2, g = lane >> 2, t = lane & 3;
    int row0 = blockIdx.x * 64;
#pragma unroll
    for (int kc = 0; kc < 4; kc++) {
        float4 xr[4];
#pragma unroll
        for (int i = 0; i < 4; i++) {
            int idx = tid + i * 256;
            int r = idx >> 4, q4 = idx & 15;
            int gr = row0 + r;
            xr[i] = (gr < Nn) ? *(const float4*)&x[(size_t)gr * INF + kc * 64 + q4 * 4]
                              : make_float4(0.f, 0.f, 0.f, 0.f);
        }
#pragma unroll
        for (int i = 0; i < 4; i++) {
            int idx = tid + i * 256;
            int r = idx >> 4, q4 = idx & 15;
            unsigned h0, l0, h1, l1;
            bsplit2(xr[i].x, xr[i].y, h0, l0);
            bsplit2(xr[i].z, xr[i].w, h1, l1);
            int pos0 = kc * 2048 + aFragPos(r, q4 * 2);
            int pos1 = kc * 2048 + aFragPos(r, q4 * 2 + 1);
            smf[pos0] = h0; smf[8192 + pos0] = l0;
            smf[pos1] = h1; smf[8192 + pos1] = l1;
        }
    }
    __syncthreads();
    float acc[4][4] = {};
#pragma unroll
    for (int u = 0; u < 16; u++) {
        int kc = u >> 2, kt = u & 3;
        int abase = kc * 2048 + ((rw * 4 + kt) * 32 + lane) * 4;
        uint4 ah = *(const uint4*)&smf[abase];
        uint4 al = *(const uint4*)&smf[8192 + abase];
        const unsigned* wh = g_w0h + kc * 2048;
        const unsigned* wl = g_w0l + kc * 2048;
#pragma unroll
        for (int nt = 0; nt < 4; nt++) {
            int off = ((kt * 8 + cw * 4 + nt) * 32 + lane) * 2;
            uint2 bh = *(const uint2*)&wh[off];
            uint2 bl = *(const uint2*)&wl[off];
            mma16(acc[nt], (const unsigned*)&ah, (const unsigned*)&bh);
            mma16(acc[nt], (const unsigned*)&ah, (const unsigned*)&bl);
            mma16(acc[nt], (const unsigned*)&al, (const unsigned*)&bh);
        }
    }
    __syncthreads();
#pragma unroll
    for (int nt = 0; nt < 4; nt++) {
        int c0 = cw * 32 + nt * 8 + t * 2;
        float b0v = bias[c0], b1v = bias[c0 + 1];
        int r0 = rw * 16 + g, r1 = r0 + 8;
        scr[r0 * 68 + c0] = acc[nt][0] + b0v; scr[r0 * 68 + c0 + 1] = acc[nt][1] + b1v;
        scr[r1 * 68 + c0] = acc[nt][2] + b0v; scr[r1 * 68 + c0 + 1] = acc[nt][3] + b1v;
    }
    __syncthreads();
    int r = tid >> 2, sub = tid & 3;
    float vbuf[16];
    float s = 0.f, sq = 0.f;
#pragma unroll
    for (int j = 0; j < 16; j++) { float v = scr[r * 68 + sub * 16 + j]; vbuf[j] = v; s += v; sq += v * v; }
    s += __shfl_xor_sync(FULL, s, 1); sq += __shfl_xor_sync(FULL, sq, 1);
    s += __shfl_xor_sync(FULL, s, 2); sq += __shfl_xor_sync(FULL, sq, 2);
    float mu = s * 0.015625f;
    float var = sq * 0.015625f - mu * mu;
    float rs = rsqrtf(var + EPSL);
    int gr = row0 + r;
    if (gr < Nn) {
        float y[16];
#pragma unroll
        for (int j = 0; j < 16; j++) {
            int c = sub * 16 + j;
            float yy = (vbuf[j] - mu) * rs * lnw[c] + lnb[c];
            yy = fmaxf(yy, 0.f);
            y[j] = yy;
            g_prev[(size_t)gr * HIDD + c] = yy;
        }
#pragma unroll
        for (int jp = 0; jp < 8; jp++) {
            unsigned h, l; bsplit2(y[2 * jp], y[2 * jp + 1], h, l);
            g_hh[(size_t)gr * 32 + sub * 8 + jp] = h;
            g_hl[(size_t)gr * 32 + sub * 8 + jp] = l;
        }
    }
}

// ---------------- CSR build ----------------
__global__ void k_zcnt() { int i = blockIdx.x * 256 + threadIdx.x; if (i < Nn) g_cnt[i] = 0; }
__global__ void k_count(const int* __restrict__ col) {
    int e = blockIdx.x * 256 + threadIdx.x;
    if (e < Ee) atomicAdd(&g_cnt[col[e]], 1);
}
__global__ void k_rsqk() {
    int i = blockIdx.x * 256 + threadIdx.x;
    if (i < Nn) { int c = g_cnt[i]; g_rsq[i] = c > 0 ? rsqrtf((float)c) : 0.f; }
}
__device__ __forceinline__ int blockScanIncl(int val, int* wsum) {
    int lane = threadIdx.x & 31, wid = threadIdx.x >> 5;
#pragma unroll
    for (int o = 1; o < 32; o <<= 1) {
        int n = __shfl_up_sync(FULL, val, o);
        if (lane >= o) val += n;
    }
    if (lane == 31) wsum[wid] = val;
    __syncthreads();
    if (wid == 0) {
        int nw = blockDim.x >> 5;
        int w = (lane < nw) ? wsum[lane] : 0;
#pragma unroll
        for (int o = 1; o < 32; o <<= 1) {
            int n = __shfl_up_sync(FULL, w, o);
            if (lane >= o) w += n;
        }
        wsum[lane] = w;
    }
    __syncthreads();
    return val + (wid > 0 ? wsum[wid - 1] : 0);
}
__global__ void k_scan1() {
    __shared__ int wsum[32];
    int i = blockIdx.x * 256 + threadIdx.x;
    int v = (i < Nn) ? g_cnt[i] : 0;
    int incl = blockScanIncl(v, wsum);
    if (i < Nn) g_ptr[i] = incl - v;
    if (threadIdx.x == 255) g_blk[blockIdx.x] = incl;
}
__global__ void k_scan2() {
    __shared__ int wsum[32];
    const int NB = (Nn + 255) / 256;
    int v = (threadIdx.x < NB) ? g_blk[threadIdx.x] : 0;
    int incl = blockScanIncl(v, wsum);
    if (threadIdx.x < NB) g_blk[threadIdx.x] = incl - v;
}
__global__ void k_scan3() {
    int i = blockIdx.x * 256 + threadIdx.x;
    if (i < Nn) {
        int p = g_ptr[i] + g_blk[i >> 8];
        g_ptr[i] = p; g_cur[i] = p;
    }
    if (i == 0) g_ptr[Nn] = Ee;
}
__global__ void k_fill(const int* __restrict__ row, const int* __restrict__ col) {
    int e = blockIdx.x * 256 + threadIdx.x;
    if (e < Ee) {
        int c = col[e];
        int p = atomicAdd(&g_cur[c], 1);
        g_erow[p] = row[e];
    }
}

// ---------------- per-layer reduction zero ----------------
__global__ void k_zero_red() {
    int i = blockIdx.x * blockDim.x + threadIdx.x;
    int stride = gridDim.x * blockDim.x;
    for (int j = i; j < 8192; j += stride) g_kvs[j] = 0.f;
    if (i < HD) { g_sumK[i] = 0.f; g_sumV[i] = 0.f; }
    if (i < 2) g_sums[i] = 0.f;
}

// ---------------- QKV: 128-row tiles, B from global, packed epilogues ----------------
__global__ __launch_bounds__(256, 2) void k_qkv(int layer, const float* __restrict__ bq,
                      const float* __restrict__ bk, const float* __restrict__ bv) {
    extern __shared__ __align__(16) unsigned smd[];   // AH 4096 | AL 4096 | E 4608
    unsigned* E = &smd[8192];
    float* Ef = (float*)E;
    __shared__ float sK[128], sV[128];
    int tid = threadIdx.x, lane = tid & 31, warp = tid >> 5;
    int rw = warp & 3, cw = warp >> 2, g = lane >> 2, t = lane & 3;
    int row0 = blockIdx.x * 128;
    const unsigned* wfh = g_wfh + layer * 12288;
    const unsigned* wfl = g_wfl + layer * 12288;
    if (tid < 128) { sK[tid] = 0.f; sV[tid] = 0.f; }
#pragma unroll
    for (int i = 0; i < 16; i++) {
        int idx = tid + i * 256;
        int r = idx >> 5, p = idx & 31;
        int gr = row0 + r;
        unsigned hv = 0, lv = 0;
        if (gr < Nn) { hv = g_hh[(size_t)gr * 32 + p]; lv = g_hl[(size_t)gr * 32 + p]; }
        int pos = (r >> 6) * 2048 + aFragPos(r & 63, p);
        smd[pos] = hv; smd[4096 + pos] = lv;
    }
    __syncthreads();
    bool rok[2][2];
#pragma unroll
    for (int tl = 0; tl < 2; tl++) {
        rok[tl][0] = (row0 + tl * 64 + rw * 16 + g) < Nn;
        rok[tl][1] = (row0 + tl * 64 + rw * 16 + g + 8) < Nn;
    }
    float q2 = 0.f, k2 = 0.f;
    float vk0[2][4][4];
#pragma unroll
    for (int ch = 0; ch < 6; ch++) {
        int mat = ch >> 1, cc2 = ch & 1;
        const float* B = mat == 0 ? bq : (mat == 1 ? bk : bv);
        bool split = (mat == 2);
        const unsigned* wh = wfh + ch * 2048;
        const unsigned* wl = wfl + ch * 2048;
        float acc[2][4][4] = {};
#pragma unroll
        for (int kt = 0; kt < 4; kt++) {
            uint4 ah0 = *(uint4*)&smd[((rw * 4 + kt) * 32 + lane) * 4];
            uint4 ah1 = *(uint4*)&smd[2048 + ((rw * 4 + kt) * 32 + lane) * 4];
            uint4 al0, al1;
            if (split) {
                al0 = *(uint4*)&smd[4096 + ((rw * 4 + kt) * 32 + lane) * 4];
                al1 = *(uint4*)&smd[6144 + ((rw * 4 + kt) * 32 + lane) * 4];
            }
#pragma unroll
            for (int nt = 0; nt < 4; nt++) {
                int off = ((kt * 8 + cw * 4 + nt) * 32 + lane) * 2;
                uint2 bh = *(const uint2*)&wh[off];
                mma16(acc[0][nt], (const unsigned*)&ah0, (const unsigned*)&bh);
                mma16(acc[1][nt], (const unsigned*)&ah1, (const unsigned*)&bh);
                if (split) {
                    uint2 bl = *(const uint2*)&wl[off];
                    mma16(acc[0][nt], (const unsigned*)&ah0, (const unsigned*)&bl);
                    mma16(acc[0][nt], (const unsigned*)&al0, (const unsigned*)&bh);
                    mma16(acc[1][nt], (const unsigned*)&ah1, (const unsigned*)&bl);
                    mma16(acc[1][nt], (const unsigned*)&al1, (const unsigned*)&bh);
                }
            }
        }
#pragma unroll
        for (int nt = 0; nt < 4; nt++) {
            int cgl = cc2 * 64 + cw * 32 + nt * 8 + t * 2;
            float b0v = B[cgl], b1v = B[cgl + 1];
            float c0s = 0.f, c1s = 0.f;
#pragma unroll
            for (int tl = 0; tl < 2; tl++) {
                acc[tl][nt][0] += b0v; acc[tl][nt][1] += b1v;
                acc[tl][nt][2] += b0v; acc[tl][nt][3] += b1v;
                float v00 = rok[tl][0] ? acc[tl][nt][0] : 0.f;
                float v01 = rok[tl][0] ? acc[tl][nt][1] : 0.f;
                float v10 = rok[tl][1] ? acc[tl][nt][2] : 0.f;
                float v11 = rok[tl][1] ? acc[tl][nt][3] : 0.f;
                if (mat == 0)      q2 += v00 * v00 + v01 * v01 + v10 * v10 + v11 * v11;
                else if (mat == 1) k2 += v00 * v00 + v01 * v01 + v10 * v10 + v11 * v11;
                if (mat >= 1) { c0s += v00 + v10; c1s += v01 + v11; }
            }
            if (mat >= 1) {
                c0s += __shfl_xor_sync(FULL, c0s, 4);  c1s += __shfl_xor_sync(FULL, c1s, 4);
                c0s += __shfl_xor_sync(FULL, c0s, 8);  c1s += __shfl_xor_sync(FULL, c1s, 8);
                c0s += __shfl_xor_sync(FULL, c0s, 16); c1s += __shfl_xor_sync(FULL, c1s, 16);
                if (g == 0) {
                    float* sd = (mat == 1) ? sK : sV;
                    atomicAdd(&sd[cgl], c0s);
                    atomicAdd(&sd[cgl + 1], c1s);
                }
            }
        }
        int r0 = rw * 16 + g, r1 = r0 + 8;
        if (mat == 0) {
            __syncthreads();
#pragma unroll
            for (int tl = 0; tl < 2; tl++)
#pragma unroll
                for (int nt = 0; nt < 4; nt++) {
                    int p = cw * 16 + nt * 4 + t;
                    E[tl * 2048 + aFragPos(r0, p)] = packbf2(acc[tl][nt][0], acc[tl][nt][1]);
                    E[tl * 2048 + aFragPos(r1, p)] = packbf2(acc[tl][nt][2], acc[tl][nt][3]);
                }
            __syncthreads();
#pragma unroll
            for (int i = 0; i < 4; i++) {
                int u = (tid + i * 256) * 4;
                int tile = u >> 11, w = u & 2047;
                *(uint4*)&g_qf[(size_t)(blockIdx.x * 2 + tile) * 4096 + cc2 * 2048 + w] =
                    *(uint4*)&E[u];
            }
        } else {
            unsigned* dst = (mat == 1) ? g_kp : g_vp;
#pragma unroll
            for (int tl = 0; tl < 2; tl++) {
                __syncthreads();
#pragma unroll
                for (int nt = 0; nt < 4; nt++) {
                    int p = cw * 16 + nt * 4 + t;
                    E[r0 * 36 + p] = packbf2(acc[tl][nt][0], acc[tl][nt][1]);
                    E[r1 * 36 + p] = packbf2(acc[tl][nt][2], acc[tl][nt][3]);
                }
                __syncthreads();
#pragma unroll
                for (int i = 0; i < 2; i++) {
                    int idx4 = tid + i * 256;
                    int r = idx4 >> 3, p4 = idx4 & 7;
                    int gr = row0 + tl * 64 + r;
                    if (gr < Nn)
                        *(uint4*)&dst[(size_t)gr * 64 + cc2 * 32 + p4 * 4] =
                            *(uint4*)&E[r * 36 + p4 * 4];
                }
            }
            if (mat == 2) {
                if (cc2 == 0) {
#pragma unroll
                    for (int tl = 0; tl < 2; tl++)
#pragma unroll
                        for (int nt = 0; nt < 4; nt++)
#pragma unroll
                            for (int j = 0; j < 4; j++) vk0[tl][nt][j] = acc[tl][nt][j];
                } else {
#pragma unroll
                    for (int tl = 0; tl < 2; tl++) {
                        __syncthreads();
#pragma unroll
                        for (int nt = 0; nt < 4; nt++) {
                            int c0 = cw * 32 + nt * 8 + 2 * t;
                            Ef[r0 * 72 + c0]     = 0.5f * (vk0[tl][nt][0] + acc[tl][nt][0]);
                            Ef[r0 * 72 + c0 + 1] = 0.5f * (vk0[tl][nt][1] + acc[tl][nt][1]);
                            Ef[r1 * 72 + c0]     = 0.5f * (vk0[tl][nt][2] + acc[tl][nt][2]);
                            Ef[r1 * 72 + c0 + 1] = 0.5f * (vk0[tl][nt][3] + acc[tl][nt][3]);
                        }
                        __syncthreads();
#pragma unroll
                        for (int i = 0; i < 4; i++) {
                            int idx = tid + i * 256;
                            int r = idx >> 4, c4 = idx & 15;
                            int gr = row0 + tl * 64 + r;
                            if (gr < Nn)
                                *(float4*)&g_vm[(size_t)gr * 64 + c4 * 4] =
                                    *(float4*)&Ef[r * 72 + c4 * 4];
                        }
                    }
                }
            }
        }
    }
#pragma unroll
    for (int o = 16; o > 0; o >>= 1) {
        q2 += __shfl_xor_sync(FULL, q2, o);
        k2 += __shfl_xor_sync(FULL, k2, o);
    }
    if (lane == 0) { atomicAdd(&g_sums[0], q2); atomicAdd(&g_sums[1], k2); }
    __syncthreads();
    if (tid < 128) { atomicAdd(&g_sumK[tid], sK[tid]); atomicAdd(&g_sumV[tid], sV[tid]); }
}

// ---------------- kvs = k^T v : packed bf16 inputs ----------------
__global__ void k_reduce() {
    __shared__ __align__(16) unsigned kraw[2048];
    __shared__ __align__(16) unsigned uraw[2048];
    __shared__ __align__(16) unsigned afr[2048];
    __shared__ __align__(16) unsigned bfr[2048];
    int tid = threadIdx.x, lane = tid & 31, warp = tid >> 5;
    int h = warp >> 2, mt = warp & 3;
    int t = lane & 3, g = lane >> 2;
    float acc[8][4] = {};
    const int NT = Nn / 32;
    for (int tt = blockIdx.x; tt < NT; tt += gridDim.x) {
        __syncthreads();
#pragma unroll
        for (int i = 0; i < 2; i++) {
            int idx4 = tid + i * 256;
            int n = idx4 >> 4, p4 = idx4 & 15;
            *(uint4*)&kraw[n * 64 + p4 * 4] =
                *(const uint4*)&g_kp[(size_t)(tt * 32 + n) * 64 + p4 * 4];
            *(uint4*)&uraw[n * 64 + p4 * 4] =
                *(const uint4*)&g_vp[(size_t)(tt * 32 + n) * 64 + p4 * 4];
        }
        __syncthreads();
#pragma unroll
        for (int i = 0; i < 8; i++) {
            int idx = tid + i * 256;
            int j = idx & 3, ln = (idx >> 2) & 31, mtt = (idx >> 7) & 3,
                ks = (idx >> 9) & 1, hh = (idx >> 10) & 1;
            int lt = ln & 3, lg = ln >> 2;
            int m = mtt * 16 + lg + (j & 1) * 8;
            int n0 = ks * 16 + 2 * lt + (j >> 1) * 8;
            int hm = hh * 64 + m;
            unsigned u0 = kraw[n0 * 64 + (hm >> 1)];
            unsigned u1 = kraw[(n0 + 1) * 64 + (hm >> 1)];
            afr[idx] = __byte_perm(u0, u1, (hm & 1) ? 0x7632 : 0x5410);
        }
#pragma unroll
        for (int i = 0; i < 8; i++) {
            int idx = tid + i * 256;
            int reg = idx & 1, ln = (idx >> 1) & 31, ntg = (idx >> 6) & 7,
                ks = (idx >> 9) & 1, hh = (idx >> 10) & 1;
            int lt = ln & 3, lg = ln >> 2;
            int hd = hh * 64 + ntg * 8 + lg;
            int n0 = ks * 16 + 2 * lt + reg * 8;
            unsigned u0 = uraw[n0 * 64 + (hd >> 1)];
            unsigned u1 = uraw[(n0 + 1) * 64 + (hd >> 1)];
            bfr[idx] = __byte_perm(u0, u1, (hd & 1) ? 0x7632 : 0x5410);
        }
        __syncthreads();
#pragma unroll
        for (int ks = 0; ks < 2; ks++) {
            uint4 a = *(uint4*)&afr[((h * 2 + ks) * 4 + mt) * 128 + lane * 4];
#pragma unroll
            for (int nt = 0; nt < 8; nt++) {
                uint2 b = *(uint2*)&bfr[(((h * 2 + ks) * 8 + nt) * 32 + lane) * 2];
                mma16(acc[nt], (const unsigned*)&a, (const unsigned*)&b);
            }
        }
    }
#pragma unroll
    for (int nt = 0; nt < 8; nt++) {
        int c0 = nt * 8 + 2 * t;
        int r0 = mt * 16 + g, r1 = r0 + 8;
        atomicAdd(&g_kvs[h * 4096 + r0 * 64 + c0],     acc[nt][0]);
        atomicAdd(&g_kvs[h * 4096 + r0 * 64 + c0 + 1], acc[nt][1]);
        atomicAdd(&g_kvs[h * 4096 + r1 * 64 + c0],     acc[nt][2]);
        atomicAdd(&g_kvs[h * 4096 + r1 * 64 + c0 + 1], acc[nt][3]);
    }
}

// ---------------- pack kvs (+ sumK as col 64) into B-fragment order ----------------
__global__ void k_pkvs() {
    int gid = blockIdx.x * 256 + threadIdx.x;
    if (gid >= 4608) return;
    int h = gid / 2304, rem = gid % 2304;
    int reg = rem & 1, ln = (rem >> 1) & 31, ntg = (rem >> 6) % 9, kt = rem / 576;
    int lt = ln & 3, lg = ln >> 2;
    int m = kt * 16 + reg * 8 + 2 * lt;
    unsigned val;
    if (ntg < 8) {
        int c = ntg * 8 + lg;
        val = packbf2(g_kvs[h * 4096 + m * 64 + c], g_kvs[h * 4096 + (m + 1) * 64 + c]);
    } else {
        val = (lg == 0) ? packbf2(g_sumK[h * 64 + m], g_sumK[h * 64 + m + 1]) : 0u;
    }
    g_kvsp[gid] = val;
}

// ---------------- fused attention + GCN gather (smem-staged edges) + LN ----------------
__global__ void k_attnc(const float* __restrict__ lnw, const float* __restrict__ lnb) {
    __shared__ float scrf[64 * 68];
    __shared__ float sVs[128];
    __shared__ float denS[128];
    __shared__ int   sE[EMAX];
    __shared__ float sWt[EMAX];
    int tid = threadIdx.x, lane = tid & 31, warp = tid >> 5;
    int rw = warp & 3, cw = warp >> 2, g = lane >> 2, t = lane & 3;
    int row0 = blockIdx.x * 64;
    int e0 = g_ptr[row0];
    int rend = (row0 + 64 < Nn) ? row0 + 64 : Nn;
    int nE = g_ptr[rend] - e0;
    bool staged = (nE <= EMAX);
    if (staged) {
        for (int i = tid; i < nE; i += 256) {
            int rr = g_erow[e0 + i];
            sE[i] = rr;
            sWt[i] = g_rsq[rr];
        }
    }
    float sc = rsqrtf(g_sums[0] * g_sums[1]);
    if (tid < 128) sVs[tid] = g_sumV[tid];
    float acc0[5][4] = {}, acc1[5][4] = {};
    int ntn = 4 + cw;
#pragma unroll
    for (int kt = 0; kt < 4; kt++) {
        uint4 a = *(const uint4*)&g_qf[(size_t)blockIdx.x * 4096 + ((rw * 4 + kt) * 32 + lane) * 4];
#pragma unroll
        for (int nt = 0; nt < 5; nt++) {
            if (nt < ntn) {
                int ntg = cw * 4 + nt;
                uint2 b = *(const uint2*)&g_kvsp[((kt * 9 + ntg) * 32 + lane) * 2];
                mma16(acc0[nt], (const unsigned*)&a, (const unsigned*)&b);
            }
        }
    }
#pragma unroll
    for (int kt = 0; kt < 4; kt++) {
        uint4 a = *(const uint4*)&g_qf[(size_t)blockIdx.x * 4096 + 2048 + ((rw * 4 + kt) * 32 + lane) * 4];
#pragma unroll
        for (int nt = 0; nt < 5; nt++) {
            if (nt < ntn) {
                int ntg = cw * 4 + nt;
                uint2 b = *(const uint2*)&g_kvsp[2304 + ((kt * 9 + ntg) * 32 + lane) * 2];
                mma16(acc1[nt], (const unsigned*)&a, (const unsigned*)&b);
            }
        }
    }
    if (cw == 1 && t == 0) {
        int r0 = rw * 16 + g;
        denS[r0]          = acc0[4][0] * sc + (float)Nn;
        denS[r0 + 8]      = acc0[4][2] * sc + (float)Nn;
        denS[64 + r0]     = acc1[4][0] * sc + (float)Nn;
        denS[64 + r0 + 8] = acc1[4][2] * sc + (float)Nn;
    }
    __syncthreads();
#pragma unroll
    for (int nt = 0; nt < 4; nt++) {
        int c = cw * 32 + nt * 8 + 2 * t;
        int r0 = rw * 16 + g, r1 = r0 + 8;
        float d00 = denS[r0], d01 = denS[r1];
        float d10 = denS[64 + r0], d11 = denS[64 + r1];
        scrf[r0 * 68 + c]     = 0.5f * ((acc0[nt][0] * sc + sVs[c])     / d00 + (acc1[nt][0] * sc + sVs[64 + c])     / d10);
        scrf[r0 * 68 + c + 1] = 0.5f * ((acc0[nt][1] * sc + sVs[c + 1]) / d00 + (acc1[nt][1] * sc + sVs[64 + c + 1]) / d10);
        scrf[r1 * 68 + c]     = 0.5f * ((acc0[nt][2] * sc + sVs[c])     / d01 + (acc1[nt][2] * sc + sVs[64 + c])     / d11);
        scrf[r1 * 68 + c + 1] = 0.5f * ((acc0[nt][3] * sc + sVs[c + 1]) / d01 + (acc1[nt][3] * sc + sVs[64 + c + 1]) / d11);
    }
    __syncthreads();
    int half = lane >> 4, hl = lane & 15;
#pragma unroll
    for (int pass = 0; pass < 4; pass++) {
        int nl = pass * 16 + warp * 2 + half;
        int n = row0 + nl;
        if (n < Nn) {
            int p0 = g_ptr[n], p1 = g_ptr[n + 1];
            float rn = g_rsq[n];
            float ax = 0.f, ay = 0.f, az = 0.f, aw = 0.f;
            if (staged) {
                int q = p0 - e0, q1 = p1 - e0;
                for (; q + 4 <= q1; q += 4) {
                    int r0 = sE[q], r1 = sE[q + 1], r2 = sE[q + 2], r3 = sE[q + 3];
                    float w0 = rn * sWt[q],     w1 = rn * sWt[q + 1];
                    float w2 = rn * sWt[q + 2], w3 = rn * sWt[q + 3];
                    float4 va = *(const float4*)&g_vm[(size_t)r0 * 64 + hl * 4];
                    float4 vb = *(const float4*)&g_vm[(size_t)r1 * 64 + hl * 4];
                    float4 vc = *(const float4*)&g_vm[(size_t)r2 * 64 + hl * 4];
                    float4 vd = *(const float4*)&g_vm[(size_t)r3 * 64 + hl * 4];
                    ax += w0 * va.x + w1 * vb.x + w2 * vc.x + w3 * vd.x;
                    ay += w0 * va.y + w1 * vb.y + w2 * vc.y + w3 * vd.y;
                    az += w0 * va.z + w1 * vb.z + w2 * vc.z + w3 * vd.z;
                    aw += w0 * va.w + w1 * vb.w + w2 * vc.w + w3 * vd.w;
                }
                for (; q < q1; q++) {
                    int r0 = sE[q];
                    float w0 = rn * sWt[q];
                    float4 va = *(const float4*)&g_vm[(size_t)r0 * 64 + hl * 4];
                    ax += w0 * va.x; ay += w0 * va.y; az += w0 * va.z; aw += w0 * va.w;
                }
            } else {
                for (int e = p0; e < p1; e++) {
                    int r0 = g_erow[e];
                    float w0 = rn * g_rsq[r0];
                    float4 va = *(const float4*)&g_vm[(size_t)r0 * 64 + hl * 4];
                    ax += w0 * va.x; ay += w0 * va.y; az += w0 * va.z; aw += w0 * va.w;
                }
            }
            float4 ov = *(const float4*)&scrf[nl * 68 + hl * 4];
            float4 pv = *(const float4*)&g_prev[(size_t)n * HIDD + hl * 4];
            float4 hv;
            hv.x = 0.5f * (ov.x + ax) + 0.5f * pv.x;
            hv.y = 0.5f * (ov.y + ay) + 0.5f * pv.y;
            hv.z = 0.5f * (ov.z + az) + 0.5f * pv.z;
            hv.w = 0.5f * (ov.w + aw) + 0.5f * pv.w;
            float s = hv.x + hv.y + hv.z + hv.w;
            float sq = hv.x * hv.x + hv.y * hv.y + hv.z * hv.z + hv.w * hv.w;
#pragma unroll
            for (int o = 1; o < 16; o <<= 1) {
                s += __shfl_xor_sync(FULL, s, o);
                sq += __shfl_xor_sync(FULL, sq, o);
            }
            float mu = s * 0.015625f;
            float var = sq * 0.015625f - mu * mu;
            float rs = rsqrtf(var + EPSL);
            float4 lw = *(const float4*)&lnw[hl * 4];
            float4 lb = *(const float4*)&lnb[hl * 4];
            float4 y;
            y.x = (hv.x - mu) * rs * lw.x + lb.x;
            y.y = (hv.y - mu) * rs * lw.y + lb.y;
            y.z = (hv.z - mu) * rs * lw.z + lb.z;
            y.w = (hv.w - mu) * rs * lw.w + lb.w;
            *(float4*)&g_h[(size_t)n * HIDD + hl * 4] = y;
            *(float4*)&g_prev[(size_t)n * HIDD + hl * 4] = y;
            unsigned h0, l0, h1, l1;
            bsplit2(y.x, y.y, h0, l0);
            bsplit2(y.z, y.w, h1, l1);
            *(uint2*)&g_hh[(size_t)n * 32 + hl * 2] = make_uint2(h0, h1);
            *(uint2*)&g_hl[(size_t)n * 32 + hl * 2] = make_uint2(l0, l1);
        }
    }
}

// ---------------- final projection ----------------
__global__ void k_fco(const float* __restrict__ w, const float* __restrict__ b,
                      float* __restrict__ out) {
    __shared__ float ws[64][40];
    __shared__ float hs[64][65];
    int tid = threadIdx.x;
    int row0 = blockIdx.x * 64;
    for (int l = tid; l < 64 * 40; l += 256) ws[l / 40][l % 40] = w[l];
#pragma unroll
    for (int l = 0; l < 4; l++) {
        int lin = tid + l * 256;
        int r = lin >> 4, c4 = lin & 15;
        int gr = row0 + r; if (gr >= Nn) gr = Nn - 1;
        float4 v = *(const float4*)&g_h[(size_t)gr * HIDD + c4 * 4];
        hs[r][c4 * 4 + 0] = v.x; hs[r][c4 * 4 + 1] = v.y;
        hs[r][c4 * 4 + 2] = v.z; hs[r][c4 * 4 + 3] = v.w;
    }
    __syncthreads();
    int r = tid & 63, cg = tid >> 6;
    float acc[10] = {};
#pragma unroll
    for (int kk = 0; kk < 64; kk++) {
        float a = hs[r][kk];
        const float* wr = &ws[kk][cg * 10];
#pragma unroll
        for (int j = 0; j < 10; j++) acc[j] += a * wr[j];
    }
    int gr = row0 + r;
    if (gr < Nn) {
#pragma unroll
        for (int j = 0; j < 10; j++)
            out[(size_t)gr * CC + cg * 10 + j] = acc[j] + b[cg * 10 + j];
    }
}

// ---------------- launcher: CSR chain forked onto a side stream ----------------
extern "C" void kernel_launch(void* const* d_in, const int* in_sizes, int n_in,
                              void* d_out, int out_size) {
    (void)in_sizes; (void)n_in; (void)out_size;
    const float* x     = (const float*)d_in[0];
    const int*   ei    = (const int*)d_in[1];
    const float* fc0_w = (const float*)d_in[2];
    const float* fc0_b = (const float*)d_in[3];
    const float* ln_w  = (const float*)d_in[4];
    const float* ln_b  = (const float*)d_in[5];
    const float* Wq    = (const float*)d_in[6];
    const float* Wk    = (const float*)d_in[7];
    const float* Wv    = (const float*)d_in[8];
    const float* bq    = (const float*)d_in[9];
    const float* bk    = (const float*)d_in[10];
    const float* bv    = (const float*)d_in[11];
    const float* fco_w = (const float*)d_in[12];
    const float* fco_b = (const float*)d_in[13];
    float* out = (float*)d_out;

    const int GB = 1563;
    const int NB = (Nn + 255) / 256;
    const int EB = (Ee + 255) / 256;
    const int QSM = 51200;
    const int FSM = 65536;

    cudaFuncSetAttribute(k_qkv, cudaFuncAttributeMaxDynamicSharedMemorySize, QSM);
    cudaFuncSetAttribute(k_fc0, cudaFuncAttributeMaxDynamicSharedMemorySize, FSM);

    cudaStream_t s2;
    cudaStreamCreateWithFlags(&s2, cudaStreamNonBlocking);
    cudaEvent_t evA, evB;
    cudaEventCreateWithFlags(&evA, cudaEventDisableTiming);
    cudaEventCreateWithFlags(&evB, cudaEventDisableTiming);

    // fork: CSR build runs concurrently with fc0/qkv chain
    cudaEventRecord(evA, 0);
    cudaStreamWaitEvent(s2, evA, 0);
    k_zcnt<<<NB, 256, 0, s2>>>();
    k_count<<<EB, 256, 0, s2>>>(ei + Ee);
    k_rsqk<<<NB, 256, 0, s2>>>();
    k_scan1<<<NB, 256, 0, s2>>>();
    k_scan2<<<1, 512, 0, s2>>>();
    k_scan3<<<NB, 256, 0, s2>>>();
    k_fill<<<EB, 256, 0, s2>>>(ei, ei + Ee);
    cudaEventRecord(evB, s2);

    // main chain (default stream)
    k_prep<<<128, 256>>>(fc0_w, Wq, Wk, Wv);
    k_zero_red<<<34, 256>>>();
    k_fc0<<<GB, 256, FSM>>>(x, fc0_b, ln_w, ln_b);              // profile slot
    k_qkv<<<QKVB, 256, QSM>>>(0, bq, bk, bv);
    k_reduce<<<320, 256>>>();
    k_pkvs<<<18, 256>>>();
    cudaStreamWaitEvent(0, evB, 0);                              // join before gather
    k_attnc<<<GB, 256>>>(ln_w + HIDD, ln_b + HIDD);
    k_zero_red<<<34, 256>>>();
    k_qkv<<<QKVB, 256, QSM>>>(1, bq + HD, bk + HD, bv + HD);
    k_reduce<<<320, 256>>>();
    k_pkvs<<<18, 256>>>();
    k_attnc<<<GB, 256>>>(ln_w + 2 * HIDD, ln_b + 2 * HIDD);
    k_fco<<<GB, 256>>>(fco_w, fco_b, out);
}

// round 15
// speedup vs baseline: 1.0562x; 1.0125x over previous
#include <cuda_runtime.h>

#define Nn    100000
#define Ee    800000
#define INF   256
#define HIDD  64
#define HD    128
#define CC    40
#define EPSL  1e-5f
#define FULL  0xffffffffu
#define GBLK  1564
#define QKVB  782
#define EMAX  2560

// ---------------- scratch ----------------
__device__ float g_prev[Nn * HIDD];
__device__ float g_vm[Nn * HIDD];
__device__ float g_rsq[Nn];
__device__ float g_kvs[2 * HIDD * HIDD];
__device__ float g_sumK[HD];
__device__ float g_sumV[HD];
__device__ float g_sums[2];
__device__ int   g_cnt[Nn];
__device__ int   g_ptr[Nn + 1];
__device__ int   g_cur[Nn];
__device__ int   g_erow[Ee];
__device__ int   g_blk[512];
__device__ unsigned g_hh[Nn * 32];
__device__ unsigned g_hl[Nn * 32];
__device__ unsigned g_qf[(size_t)GBLK * 4096];
__device__ unsigned g_kp[Nn * 64];
__device__ unsigned g_vp[Nn * 64];
__device__ unsigned g_kvsp[4608];
__device__ unsigned g_w0h[8192], g_w0l[8192];
__device__ unsigned g_wfh[24576], g_wfl[24576];

// ---------------- bf16 helpers ----------------
__device__ __forceinline__ unsigned packbf2(float f0, float f1) {
    unsigned r; asm("cvt.rn.bf16x2.f32 %0, %1, %2;" : "=r"(r) : "f"(f1), "f"(f0)); return r;
}
__device__ __forceinline__ void bsplit2(float f0, float f1, unsigned& h, unsigned& l) {
    h = packbf2(f0, f1);
    float h0 = __uint_as_float(h << 16);
    float h1 = __uint_as_float(h & 0xffff0000u);
    l = packbf2(f0 - h0, f1 - h1);
}
__device__ __forceinline__ void mma16(float* d, const unsigned* a, const unsigned* b) {
    asm volatile("mma.sync.aligned.m16n8k16.row.col.f32.bf16.bf16.f32 "
        "{%0,%1,%2,%3}, {%4,%5,%6,%7}, {%8,%9}, {%0,%1,%2,%3};"
        : "+f"(d[0]), "+f"(d[1]), "+f"(d[2]), "+f"(d[3])
        : "r"(a[0]), "r"(a[1]), "r"(a[2]), "r"(a[3]), "r"(b[0]), "r"(b[1]));
}

// frag position for A element pair: row r (0..63), pair p (0..31)
__device__ __forceinline__ int aFragPos(int r, int p) {
    return (((r >> 4) * 4 + (p >> 3)) * 32 + ((r & 7) * 4 + (p & 3))) * 4
           + ((r >> 3) & 1) + 2 * ((p >> 2) & 1);
}

// ---------------- weight pre-split ----------------
__global__ void k_prep(const float* __restrict__ fc0_w, const float* __restrict__ Wq,
                       const float* __restrict__ Wk, const float* __restrict__ Wv) {
    int id = blockIdx.x * 256 + threadIdx.x;
    if (id < 8192) {
        int kc = id >> 11, rem = id & 2047;
        int reg = rem & 1, lane = (rem >> 1) & 31, ntg = (rem >> 6) & 7, kt = rem >> 9;
        int t = lane & 3, gg = lane >> 2;
        int k = kc * 64 + kt * 16 + reg * 8 + 2 * t;
        int c = ntg * 8 + gg;
        float f0 = fc0_w[k * HIDD + c], f1 = fc0_w[(k + 1) * HIDD + c];
        unsigned h, l; bsplit2(f0, f1, h, l);
        g_w0h[id] = h; g_w0l[id] = l;
    } else if (id < 32768) {
        int id2 = id - 8192;
        int layer = id2 / 12288, r3 = id2 % 12288;
        int mat = r3 >> 12, cc2 = (r3 >> 11) & 1, rem = r3 & 2047;
        int reg = rem & 1, lane = (rem >> 1) & 31, ntg = (rem >> 6) & 7, kt = rem >> 9;
        int t = lane & 3, gg = lane >> 2;
        const float* W = (mat == 0 ? Wq : (mat == 1 ? Wk : Wv)) + (size_t)layer * HIDD * HD;
        int k = kt * 16 + reg * 8 + 2 * t;
        int cg = cc2 * 64 + ntg * 8 + gg;
        float f0 = W[k * HD + cg], f1 = W[(k + 1) * HD + cg];
        unsigned h, l; bsplit2(f0, f1, h, l);
        g_wfh[id2] = h; g_wfl[id2] = l;
    }
}

// ---------------- fc0: all-A-upfront, ONE sync, barrier-free mainloop ----------------
__global__ void k_fc0(const float* __restrict__ x, const float* __restrict__ bias,
                      const float* __restrict__ lnw, const float* __restrict__ lnb) {
    extern __shared__ __align__(16) unsigned smf[];
    float* scr = (float*)smf;
    int tid = threadIdx.x, lane = tid & 31, warp = tid >> 5;
    int rw = warp & 3, cw = warp >> 2, g = lane >> 2, t = lane & 3;
    int row0 = blockIdx.x * 64;
#pragma unroll
    for (int kc = 0; kc < 4; kc++) {
        float4 xr[4];
#pragma unroll
        for (int i = 0; i < 4; i++) {
            int idx = tid + i * 256;
            int r = idx >> 4, q4 = idx & 15;
            int gr = row0 + r;
            xr[i] = (gr < Nn) ? *(const float4*)&x[(size_t)gr * INF + kc * 64 + q4 * 4]
                              : make_float4(0.f, 0.f, 0.f, 0.f);
        }
#pragma unroll
        for (int i = 0; i < 4; i++) {
            int idx = tid + i * 256;
            int r = idx >> 4, q4 = idx & 15;
            unsigned h0, l0, h1, l1;
            bsplit2(xr[i].x, xr[i].y, h0, l0);
            bsplit2(xr[i].z, xr[i].w, h1, l1);
            int pos0 = kc * 2048 + aFragPos(r, q4 * 2);
            int pos1 = kc * 2048 + aFragPos(r, q4 * 2 + 1);
            smf[pos0] = h0; smf[8192 + pos0] = l0;
            smf[pos1] = h1; smf[8192 + pos1] = l1;
        }
    }
    __syncthreads();
    float acc[4][4] = {};
#pragma unroll
    for (int u = 0; u < 16; u++) {
        int kc = u >> 2, kt = u & 3;
        int abase = kc * 2048 + ((rw * 4 + kt) * 32 + lane) * 4;
        uint4 ah = *(const uint4*)&smf[abase];
        uint4 al = *(const uint4*)&smf[8192 + abase];
        const unsigned* wh = g_w0h + kc * 2048;
        const unsigned* wl = g_w0l + kc * 2048;
#pragma unroll
        for (int nt = 0; nt < 4; nt++) {
            int off = ((kt * 8 + cw * 4 + nt) * 32 + lane) * 2;
            uint2 bh = *(const uint2*)&wh[off];
            uint2 bl = *(const uint2*)&wl[off];
            mma16(acc[nt], (const unsigned*)&ah, (const unsigned*)&bh);
            mma16(acc[nt], (const unsigned*)&ah, (const unsigned*)&bl);
            mma16(acc[nt], (const unsigned*)&al, (const unsigned*)&bh);
        }
    }
    __syncthreads();
#pragma unroll
    for (int nt = 0; nt < 4; nt++) {
        int c0 = cw * 32 + nt * 8 + t * 2;
        float b0v = bias[c0], b1v = bias[c0 + 1];
        int r0 = rw * 16 + g, r1 = r0 + 8;
        scr[r0 * 68 + c0] = acc[nt][0] + b0v; scr[r0 * 68 + c0 + 1] = acc[nt][1] + b1v;
        scr[r1 * 68 + c0] = acc[nt][2] + b0v; scr[r1 * 68 + c0 + 1] = acc[nt][3] + b1v;
    }
    __syncthreads();
    int r = tid >> 2, sub = tid & 3;
    float vbuf[16];
    float s = 0.f, sq = 0.f;
#pragma unroll
    for (int j = 0; j < 16; j++) { float v = scr[r * 68 + sub * 16 + j]; vbuf[j] = v; s += v; sq += v * v; }
    s += __shfl_xor_sync(FULL, s, 1); sq += __shfl_xor_sync(FULL, sq, 1);
    s += __shfl_xor_sync(FULL, s, 2); sq += __shfl_xor_sync(FULL, sq, 2);
    float mu = s * 0.015625f;
    float var = sq * 0.015625f - mu * mu;
    float rs = rsqrtf(var + EPSL);
    int gr = row0 + r;
    if (gr < Nn) {
        float y[16];
#pragma unroll
        for (int j = 0; j < 16; j++) {
            int c = sub * 16 + j;
            float yy = (vbuf[j] - mu) * rs * lnw[c] + lnb[c];
            yy = fmaxf(yy, 0.f);
            y[j] = yy;
            g_prev[(size_t)gr * HIDD + c] = yy;
        }
#pragma unroll
        for (int jp = 0; jp < 8; jp++) {
            unsigned h, l; bsplit2(y[2 * jp], y[2 * jp + 1], h, l);
            g_hh[(size_t)gr * 32 + sub * 8 + jp] = h;
            g_hl[(size_t)gr * 32 + sub * 8 + jp] = l;
        }
    }
}

// ---------------- CSR build ----------------
__global__ void k_zcnt() { int i = blockIdx.x * 256 + threadIdx.x; if (i < Nn) g_cnt[i] = 0; }
__global__ void k_count(const int* __restrict__ col) {
    int e = blockIdx.x * 256 + threadIdx.x;
    if (e < Ee) atomicAdd(&g_cnt[col[e]], 1);
}
__global__ void k_rsqk() {
    int i = blockIdx.x * 256 + threadIdx.x;
    if (i < Nn) { int c = g_cnt[i]; g_rsq[i] = c > 0 ? rsqrtf((float)c) : 0.f; }
}
__device__ __forceinline__ int blockScanIncl(int val, int* wsum) {
    int lane = threadIdx.x & 31, wid = threadIdx.x >> 5;
#pragma unroll
    for (int o = 1; o < 32; o <<= 1) {
        int n = __shfl_up_sync(FULL, val, o);
        if (lane >= o) val += n;
    }
    if (lane == 31) wsum[wid] = val;
    __syncthreads();
    if (wid == 0) {
        int nw = blockDim.x >> 5;
        int w = (lane < nw) ? wsum[lane] : 0;
#pragma unroll
        for (int o = 1; o < 32; o <<= 1) {
            int n = __shfl_up_sync(FULL, w, o);
            if (lane >= o) w += n;
        }
        wsum[lane] = w;
    }
    __syncthreads();
    return val + (wid > 0 ? wsum[wid - 1] : 0);
}
__global__ void k_scan1() {
    __shared__ int wsum[32];
    int i = blockIdx.x * 256 + threadIdx.x;
    int v = (i < Nn) ? g_cnt[i] : 0;
    int incl = blockScanIncl(v, wsum);
    if (i < Nn) g_ptr[i] = incl - v;
    if (threadIdx.x == 255) g_blk[blockIdx.x] = incl;
}
__global__ void k_scan2() {
    __shared__ int wsum[32];
    const int NB = (Nn + 255) / 256;
    int v = (threadIdx.x < NB) ? g_blk[threadIdx.x] : 0;
    int incl = blockScanIncl(v, wsum);
    if (threadIdx.x < NB) g_blk[threadIdx.x] = incl - v;
}
__global__ void k_scan3() {
    int i = blockIdx.x * 256 + threadIdx.x;
    if (i < Nn) {
        int p = g_ptr[i] + g_blk[i >> 8];
        g_ptr[i] = p; g_cur[i] = p;
    }
    if (i == 0) g_ptr[Nn] = Ee;
}
__global__ void k_fill(const int* __restrict__ row, const int* __restrict__ col) {
    int e = blockIdx.x * 256 + threadIdx.x;
    if (e < Ee) {
        int c = col[e];
        int p = atomicAdd(&g_cur[c], 1);
        g_erow[p] = row[e];
    }
}

// ---------------- per-layer reduction zero ----------------
__global__ void k_zero_red() {
    int i = blockIdx.x * blockDim.x + threadIdx.x;
    int stride = gridDim.x * blockDim.x;
    for (int j = i; j < 8192; j += stride) g_kvs[j] = 0.f;
    if (i < HD) { g_sumK[i] = 0.f; g_sumV[i] = 0.f; }
    if (i < 2) g_sums[i] = 0.f;
}

// ---------------- QKV: 128-row tiles, B from global, packed epilogues ----------------
__global__ __launch_bounds__(256, 2) void k_qkv(int layer, const float* __restrict__ bq,
                      const float* __restrict__ bk, const float* __restrict__ bv) {
    extern __shared__ __align__(16) unsigned smd[];   // AH 4096 | AL 4096 | E 4608
    unsigned* E = &smd[8192];
    float* Ef = (float*)E;
    __shared__ float sK[128], sV[128];
    int tid = threadIdx.x, lane = tid & 31, warp = tid >> 5;
    int rw = warp & 3, cw = warp >> 2, g = lane >> 2, t = lane & 3;
    int row0 = blockIdx.x * 128;
    const unsigned* wfh = g_wfh + layer * 12288;
    const unsigned* wfl = g_wfl + layer * 12288;
    if (tid < 128) { sK[tid] = 0.f; sV[tid] = 0.f; }
#pragma unroll
    for (int i = 0; i < 16; i++) {
        int idx = tid + i * 256;
        int r = idx >> 5, p = idx & 31;
        int gr = row0 + r;
        unsigned hv = 0, lv = 0;
        if (gr < Nn) { hv = g_hh[(size_t)gr * 32 + p]; lv = g_hl[(size_t)gr * 32 + p]; }
        int pos = (r >> 6) * 2048 + aFragPos(r & 63, p);
        smd[pos] = hv; smd[4096 + pos] = lv;
    }
    __syncthreads();
    bool rok[2][2];
#pragma unroll
    for (int tl = 0; tl < 2; tl++) {
        rok[tl][0] = (row0 + tl * 64 + rw * 16 + g) < Nn;
        rok[tl][1] = (row0 + tl * 64 + rw * 16 + g + 8) < Nn;
    }
    float q2 = 0.f, k2 = 0.f;
    float vk0[2][4][4];
#pragma unroll
    for (int ch = 0; ch < 6; ch++) {
        int mat = ch >> 1, cc2 = ch & 1;
        const float* B = mat == 0 ? bq : (mat == 1 ? bk : bv);
        bool split = (mat == 2);
        const unsigned* wh = wfh + ch * 2048;
        const unsigned* wl = wfl + ch * 2048;
        float acc[2][4][4] = {};
#pragma unroll
        for (int kt = 0; kt < 4; kt++) {
            uint4 ah0 = *(uint4*)&smd[((rw * 4 + kt) * 32 + lane) * 4];
            uint4 ah1 = *(uint4*)&smd[2048 + ((rw * 4 + kt) * 32 + lane) * 4];
            uint4 al0, al1;
            if (split) {
                al0 = *(uint4*)&smd[4096 + ((rw * 4 + kt) * 32 + lane) * 4];
                al1 = *(uint4*)&smd[6144 + ((rw * 4 + kt) * 32 + lane) * 4];
            }
#pragma unroll
            for (int nt = 0; nt < 4; nt++) {
                int off = ((kt * 8 + cw * 4 + nt) * 32 + lane) * 2;
                uint2 bh = *(const uint2*)&wh[off];
                mma16(acc[0][nt], (const unsigned*)&ah0, (const unsigned*)&bh);
                mma16(acc[1][nt], (const unsigned*)&ah1, (const unsigned*)&bh);
                if (split) {
                    uint2 bl = *(const uint2*)&wl[off];
                    mma16(acc[0][nt], (const unsigned*)&ah0, (const unsigned*)&bl);
                    mma16(acc[0][nt], (const unsigned*)&al0, (const unsigned*)&bh);
                    mma16(acc[1][nt], (const unsigned*)&ah1, (const unsigned*)&bl);
                    mma16(acc[1][nt], (const unsigned*)&al1, (const unsigned*)&bh);
                }
            }
        }
#pragma unroll
        for (int nt = 0; nt < 4; nt++) {
            int cgl = cc2 * 64 + cw * 32 + nt * 8 + t * 2;
            float b0v = B[cgl], b1v = B[cgl + 1];
            float c0s = 0.f, c1s = 0.f;
#pragma unroll
            for (int tl = 0; tl < 2; tl++) {
                acc[tl][nt][0] += b0v; acc[tl][nt][1] += b1v;
                acc[tl][nt][2] += b0v; acc[tl][nt][3] += b1v;
                float v00 = rok[tl][0] ? acc[tl][nt][0] : 0.f;
                float v01 = rok[tl][0] ? acc[tl][nt][1] : 0.f;
                float v10 = rok[tl][1] ? acc[tl][nt][2] : 0.f;
                float v11 = rok[tl][1] ? acc[tl][nt][3] : 0.f;
                if (mat == 0)      q2 += v00 * v00 + v01 * v01 + v10 * v10 + v11 * v11;
                else if (mat == 1) k2 += v00 * v00 + v01 * v01 + v10 * v10 + v11 * v11;
                if (mat >= 1) { c0s += v00 + v10; c1s += v01 + v11; }
            }
            if (mat >= 1) {
                c0s += __shfl_xor_sync(FULL, c0s, 4);  c1s += __shfl_xor_sync(FULL, c1s, 4);
                c0s += __shfl_xor_sync(FULL, c0s, 8);  c1s += __shfl_xor_sync(FULL, c1s, 8);
                c0s += __shfl_xor_sync(FULL, c0s, 16); c1s += __shfl_xor_sync(FULL, c1s, 16);
                if (g == 0) {
                    float* sd = (mat == 1) ? sK : sV;
                    atomicAdd(&sd[cgl], c0s);
                    atomicAdd(&sd[cgl + 1], c1s);
                }
            }
        }
        int r0 = rw * 16 + g, r1 = r0 + 8;
        if (mat == 0) {
            __syncthreads();
#pragma unroll
            for (int tl = 0; tl < 2; tl++)
#pragma unroll
                for (int nt = 0; nt < 4; nt++) {
                    int p = cw * 16 + nt * 4 + t;
                    E[tl * 2048 + aFragPos(r0, p)] = packbf2(acc[tl][nt][0], acc[tl][nt][1]);
                    E[tl * 2048 + aFragPos(r1, p)] = packbf2(acc[tl][nt][2], acc[tl][nt][3]);
                }
            __syncthreads();
#pragma unroll
            for (int i = 0; i < 4; i++) {
                int u = (tid + i * 256) * 4;
                int tile = u >> 11, w = u & 2047;
                *(uint4*)&g_qf[(size_t)(blockIdx.x * 2 + tile) * 4096 + cc2 * 2048 + w] =
                    *(uint4*)&E[u];
            }
        } else {
            unsigned* dst = (mat == 1) ? g_kp : g_vp;
#pragma unroll
            for (int tl = 0; tl < 2; tl++) {
                __syncthreads();
#pragma unroll
                for (int nt = 0; nt < 4; nt++) {
                    int p = cw * 16 + nt * 4 + t;
                    E[r0 * 36 + p] = packbf2(acc[tl][nt][0], acc[tl][nt][1]);
                    E[r1 * 36 + p] = packbf2(acc[tl][nt][2], acc[tl][nt][3]);
                }
                __syncthreads();
#pragma unroll
                for (int i = 0; i < 2; i++) {
                    int idx4 = tid + i * 256;
                    int r = idx4 >> 3, p4 = idx4 & 7;
                    int gr = row0 + tl * 64 + r;
                    if (gr < Nn)
                        *(uint4*)&dst[(size_t)gr * 64 + cc2 * 32 + p4 * 4] =
                            *(uint4*)&E[r * 36 + p4 * 4];
                }
            }
            if (mat == 2) {
                if (cc2 == 0) {
#pragma unroll
                    for (int tl = 0; tl < 2; tl++)
#pragma unroll
                        for (int nt = 0; nt < 4; nt++)
#pragma unroll
                            for (int j = 0; j < 4; j++) vk0[tl][nt][j] = acc[tl][nt][j];
                } else {
#pragma unroll
                    for (int tl = 0; tl < 2; tl++) {
                        __syncthreads();
#pragma unroll
                        for (int nt = 0; nt < 4; nt++) {
                            int c0 = cw * 32 + nt * 8 + 2 * t;
                            Ef[r0 * 72 + c0]     = 0.5f * (vk0[tl][nt][0] + acc[tl][nt][0]);
                            Ef[r0 * 72 + c0 + 1] = 0.5f * (vk0[tl][nt][1] + acc[tl][nt][1]);
                            Ef[r1 * 72 + c0]     = 0.5f * (vk0[tl][nt][2] + acc[tl][nt][2]);
                            Ef[r1 * 72 + c0 + 1] = 0.5f * (vk0[tl][nt][3] + acc[tl][nt][3]);
                        }
                        __syncthreads();
#pragma unroll
                        for (int i = 0; i < 4; i++) {
                            int idx = tid + i * 256;
                            int r = idx >> 4, c4 = idx & 15;
                            int gr = row0 + tl * 64 + r;
                            if (gr < Nn)
                                *(float4*)&g_vm[(size_t)gr * 64 + c4 * 4] =
                                    *(float4*)&Ef[r * 72 + c4 * 4];
                        }
                    }
                }
            }
        }
    }
#pragma unroll
    for (int o = 16; o > 0; o >>= 1) {
        q2 += __shfl_xor_sync(FULL, q2, o);
        k2 += __shfl_xor_sync(FULL, k2, o);
    }
    if (lane == 0) { atomicAdd(&g_sums[0], q2); atomicAdd(&g_sums[1], k2); }
    __syncthreads();
    if (tid < 128) { atomicAdd(&g_sumK[tid], sK[tid]); atomicAdd(&g_sumV[tid], sV[tid]); }
}

// ---------------- kvs = k^T v : packed bf16 inputs ----------------
__global__ void k_reduce() {
    __shared__ __align__(16) unsigned kraw[2048];
    __shared__ __align__(16) unsigned uraw[2048];
    __shared__ __align__(16) unsigned afr[2048];
    __shared__ __align__(16) unsigned bfr[2048];
    int tid = threadIdx.x, lane = tid & 31, warp = tid >> 5;
    int h = warp >> 2, mt = warp & 3;
    int t = lane & 3, g = lane >> 2;
    float acc[8][4] = {};
    const int NT = Nn / 32;
    for (int tt = blockIdx.x; tt < NT; tt += gridDim.x) {
        __syncthreads();
#pragma unroll
        for (int i = 0; i < 2; i++) {
            int idx4 = tid + i * 256;
            int n = idx4 >> 4, p4 = idx4 & 15;
            *(uint4*)&kraw[n * 64 + p4 * 4] =
                *(const uint4*)&g_kp[(size_t)(tt * 32 + n) * 64 + p4 * 4];
            *(uint4*)&uraw[n * 64 + p4 * 4] =
                *(const uint4*)&g_vp[(size_t)(tt * 32 + n) * 64 + p4 * 4];
        }
        __syncthreads();
#pragma unroll
        for (int i = 0; i < 8; i++) {
            int idx = tid + i * 256;
            int j = idx & 3, ln = (idx >> 2) & 31, mtt = (idx >> 7) & 3,
                ks = (idx >> 9) & 1, hh = (idx >> 10) & 1;
            int lt = ln & 3, lg = ln >> 2;
            int m = mtt * 16 + lg + (j & 1) * 8;
            int n0 = ks * 16 + 2 * lt + (j >> 1) * 8;
            int hm = hh * 64 + m;
            unsigned u0 = kraw[n0 * 64 + (hm >> 1)];
            unsigned u1 = kraw[(n0 + 1) * 64 + (hm >> 1)];
            afr[idx] = __byte_perm(u0, u1, (hm & 1) ? 0x7632 : 0x5410);
        }
#pragma unroll
        for (int i = 0; i < 8; i++) {
            int idx = tid + i * 256;
            int reg = idx & 1, ln = (idx >> 1) & 31, ntg = (idx >> 6) & 7,
                ks = (idx >> 9) & 1, hh = (idx >> 10) & 1;
            int lt = ln & 3, lg = ln >> 2;
            int hd = hh * 64 + ntg * 8 + lg;
            int n0 = ks * 16 + 2 * lt + reg * 8;
            unsigned u0 = uraw[n0 * 64 + (hd >> 1)];
            unsigned u1 = uraw[(n0 + 1) * 64 + (hd >> 1)];
            bfr[idx] = __byte_perm(u0, u1, (hd & 1) ? 0x7632 : 0x5410);
        }
        __syncthreads();
#pragma unroll
        for (int ks = 0; ks < 2; ks++) {
            uint4 a = *(uint4*)&afr[((h * 2 + ks) * 4 + mt) * 128 + lane * 4];
#pragma unroll
            for (int nt = 0; nt < 8; nt++) {
                uint2 b = *(uint2*)&bfr[(((h * 2 + ks) * 8 + nt) * 32 + lane) * 2];
                mma16(acc[nt], (const unsigned*)&a, (const unsigned*)&b);
            }
        }
    }
#pragma unroll
    for (int nt = 0; nt < 8; nt++) {
        int c0 = nt * 8 + 2 * t;
        int r0 = mt * 16 + g, r1 = r0 + 8;
        atomicAdd(&g_kvs[h * 4096 + r0 * 64 + c0],     acc[nt][0]);
        atomicAdd(&g_kvs[h * 4096 + r0 * 64 + c0 + 1], acc[nt][1]);
        atomicAdd(&g_kvs[h * 4096 + r1 * 64 + c0],     acc[nt][2]);
        atomicAdd(&g_kvs[h * 4096 + r1 * 64 + c0 + 1], acc[nt][3]);
    }
}

// ---------------- pack kvs (+ sumK as col 64) into B-fragment order ----------------
__global__ void k_pkvs() {
    int gid = blockIdx.x * 256 + threadIdx.x;
    if (gid >= 4608) return;
    int h = gid / 2304, rem = gid % 2304;
    int reg = rem & 1, ln = (rem >> 1) & 31, ntg = (rem >> 6) % 9, kt = rem / 576;
    int lt = ln & 3, lg = ln >> 2;
    int m = kt * 16 + reg * 8 + 2 * lt;
    unsigned val;
    if (ntg < 8) {
        int c = ntg * 8 + lg;
        val = packbf2(g_kvs[h * 4096 + m * 64 + c], g_kvs[h * 4096 + (m + 1) * 64 + c]);
    } else {
        val = (lg == 0) ? packbf2(g_sumK[h * 64 + m], g_sumK[h * 64 + m + 1]) : 0u;
    }
    g_kvsp[gid] = val;
}

// ---------------- fused attention + GCN gather + LN (+ optional final projection) ----------------
__global__ void k_attnc(const float* __restrict__ lnw, const float* __restrict__ lnb,
                        const float* __restrict__ fcow, const float* __restrict__ fcob,
                        float* __restrict__ out, int last) {
    __shared__ float scrf[64 * 68];
    __shared__ float sVs[128];
    __shared__ float denS[128];
    __shared__ int   sE[EMAX];
    __shared__ float sWt[EMAX];
    int tid = threadIdx.x, lane = tid & 31, warp = tid >> 5;
    int rw = warp & 3, cw = warp >> 2, g = lane >> 2, t = lane & 3;
    int row0 = blockIdx.x * 64;
    int e0 = g_ptr[row0];
    int rend = (row0 + 64 < Nn) ? row0 + 64 : Nn;
    int nE = g_ptr[rend] - e0;
    bool staged = (nE <= EMAX);
    if (staged) {
        for (int i = tid; i < nE; i += 256) {
            int rr = g_erow[e0 + i];
            sE[i] = rr;
            sWt[i] = g_rsq[rr];
        }
    }
    float sc = rsqrtf(g_sums[0] * g_sums[1]);
    if (tid < 128) sVs[tid] = g_sumV[tid];
    float acc0[5][4] = {}, acc1[5][4] = {};
    int ntn = 4 + cw;
#pragma unroll
    for (int kt = 0; kt < 4; kt++) {
        uint4 a = *(const uint4*)&g_qf[(size_t)blockIdx.x * 4096 + ((rw * 4 + kt) * 32 + lane) * 4];
#pragma unroll
        for (int nt = 0; nt < 5; nt++) {
            if (nt < ntn) {
                int ntg = cw * 4 + nt;
                uint2 b = *(const uint2*)&g_kvsp[((kt * 9 + ntg) * 32 + lane) * 2];
                mma16(acc0[nt], (const unsigned*)&a, (const unsigned*)&b);
            }
        }
    }
#pragma unroll
    for (int kt = 0; kt < 4; kt++) {
        uint4 a = *(const uint4*)&g_qf[(size_t)blockIdx.x * 4096 + 2048 + ((rw * 4 + kt) * 32 + lane) * 4];
#pragma unroll
        for (int nt = 0; nt < 5; nt++) {
            if (nt < ntn) {
                int ntg = cw * 4 + nt;
                uint2 b = *(const uint2*)&g_kvsp[2304 + ((kt * 9 + ntg) * 32 + lane) * 2];
                mma16(acc1[nt], (const unsigned*)&a, (const unsigned*)&b);
            }
        }
    }
    if (cw == 1 && t == 0) {
        int r0 = rw * 16 + g;
        denS[r0]          = acc0[4][0] * sc + (float)Nn;
        denS[r0 + 8]      = acc0[4][2] * sc + (float)Nn;
        denS[64 + r0]     = acc1[4][0] * sc + (float)Nn;
        denS[64 + r0 + 8] = acc1[4][2] * sc + (float)Nn;
    }
    __syncthreads();
#pragma unroll
    for (int nt = 0; nt < 4; nt++) {
        int c = cw * 32 + nt * 8 + 2 * t;
        int r0 = rw * 16 + g, r1 = r0 + 8;
        float d00 = denS[r0], d01 = denS[r1];
        float d10 = denS[64 + r0], d11 = denS[64 + r1];
        scrf[r0 * 68 + c]     = 0.5f * ((acc0[nt][0] * sc + sVs[c])     / d00 + (acc1[nt][0] * sc + sVs[64 + c])     / d10);
        scrf[r0 * 68 + c + 1] = 0.5f * ((acc0[nt][1] * sc + sVs[c + 1]) / d00 + (acc1[nt][1] * sc + sVs[64 + c + 1]) / d10);
        scrf[r1 * 68 + c]     = 0.5f * ((acc0[nt][2] * sc + sVs[c])     / d01 + (acc1[nt][2] * sc + sVs[64 + c])     / d11);
        scrf[r1 * 68 + c + 1] = 0.5f * ((acc0[nt][3] * sc + sVs[c + 1]) / d01 + (acc1[nt][3] * sc + sVs[64 + c + 1]) / d11);
    }
    __syncthreads();
    int half = lane >> 4, hl = lane & 15;
#pragma unroll
    for (int pass = 0; pass < 4; pass++) {
        int nl = pass * 16 + warp * 2 + half;
        int n = row0 + nl;
        if (n < Nn) {
            int p0 = g_ptr[n], p1 = g_ptr[n + 1];
            float rn = g_rsq[n];
            float ax = 0.f, ay = 0.f, az = 0.f, aw = 0.f;
            if (staged) {
                int q = p0 - e0, q1 = p1 - e0;
                for (; q + 4 <= q1; q += 4) {
                    int r0 = sE[q], r1 = sE[q + 1], r2 = sE[q + 2], r3 = sE[q + 3];
                    float w0 = rn * sWt[q],     w1 = rn * sWt[q + 1];
                    float w2 = rn * sWt[q + 2], w3 = rn * sWt[q + 3];
                    float4 va = *(const float4*)&g_vm[(size_t)r0 * 64 + hl * 4];
                    float4 vb = *(const float4*)&g_vm[(size_t)r1 * 64 + hl * 4];
                    float4 vc = *(const float4*)&g_vm[(size_t)r2 * 64 + hl * 4];
                    float4 vd = *(const float4*)&g_vm[(size_t)r3 * 64 + hl * 4];
                    ax += w0 * va.x + w1 * vb.x + w2 * vc.x + w3 * vd.x;
                    ay += w0 * va.y + w1 * vb.y + w2 * vc.y + w3 * vd.y;
                    az += w0 * va.z + w1 * vb.z + w2 * vc.z + w3 * vd.z;
                    aw += w0 * va.w + w1 * vb.w + w2 * vc.w + w3 * vd.w;
                }
                for (; q < q1; q++) {
                    int r0 = sE[q];
                    float w0 = rn * sWt[q];
                    float4 va = *(const float4*)&g_vm[(size_t)r0 * 64 + hl * 4];
                    ax += w0 * va.x; ay += w0 * va.y; az += w0 * va.z; aw += w0 * va.w;
                }
            } else {
                for (int e = p0; e < p1; e++) {
                    int r0 = g_erow[e];
                    float w0 = rn * g_rsq[r0];
                    float4 va = *(const float4*)&g_vm[(size_t)r0 * 64 + hl * 4];
                    ax += w0 * va.x; ay += w0 * va.y; az += w0 * va.z; aw += w0 * va.w;
                }
            }
            float4 ov = *(const float4*)&scrf[nl * 68 + hl * 4];
            float4 pv = *(const float4*)&g_prev[(size_t)n * HIDD + hl * 4];
            float4 hv;
            hv.x = 0.5f * (ov.x + ax) + 0.5f * pv.x;
            hv.y = 0.5f * (ov.y + ay) + 0.5f * pv.y;
            hv.z = 0.5f * (ov.z + az) + 0.5f * pv.z;
            hv.w = 0.5f * (ov.w + aw) + 0.5f * pv.w;
            float s = hv.x + hv.y + hv.z + hv.w;
            float sq = hv.x * hv.x + hv.y * hv.y + hv.z * hv.z + hv.w * hv.w;
#pragma unroll
            for (int o = 1; o < 16; o <<= 1) {
                s += __shfl_xor_sync(FULL, s, o);
                sq += __shfl_xor_sync(FULL, sq, o);
            }
            float mu = s * 0.015625f;
            float var = sq * 0.015625f - mu * mu;
            float rs = rsqrtf(var + EPSL);
            float4 lw = *(const float4*)&lnw[hl * 4];
            float4 lb = *(const float4*)&lnb[hl * 4];
            float4 y;
            y.x = (hv.x - mu) * rs * lw.x + lb.x;
            y.y = (hv.y - mu) * rs * lw.y + lb.y;
            y.z = (hv.z - mu) * rs * lw.z + lb.z;
            y.w = (hv.w - mu) * rs * lw.w + lb.w;
            if (last) {
                // stash y in scrf for in-block final projection
                *(float4*)&scrf[nl * 68 + hl * 4] = y;
            } else {
                *(float4*)&g_prev[(size_t)n * HIDD + hl * 4] = y;
                unsigned h0, l0, h1, l1;
                bsplit2(y.x, y.y, h0, l0);
                bsplit2(y.z, y.w, h1, l1);
                *(uint2*)&g_hh[(size_t)n * 32 + hl * 2] = make_uint2(h0, h1);
                *(uint2*)&g_hl[(size_t)n * 32 + hl * 2] = make_uint2(l0, l1);
            }
        }
    }
    if (last) {
        __syncthreads();
        // stage fco_w into the (now dead) edge-staging smem
        float* wsm = (float*)sE;   // 2560 floats = 64x40
        for (int i = tid; i < 2560; i += 256) wsm[i] = fcow[i];
        __syncthreads();
        int r = tid & 63, cg = tid >> 6;
        float acc[10] = {};
#pragma unroll
        for (int kk = 0; kk < 64; kk++) {
            float a = scrf[r * 68 + kk];
            const float* wr = &wsm[kk * 40 + cg * 10];
#pragma unroll
            for (int j = 0; j < 10; j++) acc[j] += a * wr[j];
        }
        int gr = row0 + r;
        if (gr < Nn) {
#pragma unroll
            for (int j = 0; j < 10; j++)
                out[(size_t)gr * CC + cg * 10 + j] = acc[j] + fcob[cg * 10 + j];
        }
    }
}

// ---------------- launcher: CSR chain forked onto a side stream ----------------
extern "C" void kernel_launch(void* const* d_in, const int* in_sizes, int n_in,
                              void* d_out, int out_size) {
    (void)in_sizes; (void)n_in; (void)out_size;
    const float* x     = (const float*)d_in[0];
    const int*   ei    = (const int*)d_in[1];
    const float* fc0_w = (const float*)d_in[2];
    const float* fc0_b = (const float*)d_in[3];
    const float* ln_w  = (const float*)d_in[4];
    const float* ln_b  = (const float*)d_in[5];
    const float* Wq    = (const float*)d_in[6];
    const float* Wk    = (const float*)d_in[7];
    const float* Wv    = (const float*)d_in[8];
    const float* bq    = (const float*)d_in[9];
    const float* bk    = (const float*)d_in[10];
    const float* bv    = (const float*)d_in[11];
    const float* fco_w = (const float*)d_in[12];
    const float* fco_b = (const float*)d_in[13];
    float* out = (float*)d_out;

    const int GB = 1563;
    const int NB = (Nn + 255) / 256;
    const int EB = (Ee + 255) / 256;
    const int QSM = 51200;
    const int FSM = 65536;

    cudaFuncSetAttribute(k_qkv, cudaFuncAttributeMaxDynamicSharedMemorySize, QSM);
    cudaFuncSetAttribute(k_fc0, cudaFuncAttributeMaxDynamicSharedMemorySize, FSM);

    cudaStream_t s2;
    cudaStreamCreateWithFlags(&s2, cudaStreamNonBlocking);
    cudaEvent_t evA, evB;
    cudaEventCreateWithFlags(&evA, cudaEventDisableTiming);
    cudaEventCreateWithFlags(&evB, cudaEventDisableTiming);

    // fork: CSR build runs concurrently with fc0/qkv chain
    cudaEventRecord(evA, 0);
    cudaStreamWaitEvent(s2, evA, 0);
    k_zcnt<<<NB, 256, 0, s2>>>();
    k_count<<<EB, 256, 0, s2>>>(ei + Ee);
    k_rsqk<<<NB, 256, 0, s2>>>();
    k_scan1<<<NB, 256, 0, s2>>>();
    k_scan2<<<1, 512, 0, s2>>>();
    k_scan3<<<NB, 256, 0, s2>>>();
    k_fill<<<EB, 256, 0, s2>>>(ei, ei + Ee);
    cudaEventRecord(evB, s2);

    // main chain (default stream)
    k_prep<<<128, 256>>>(fc0_w, Wq, Wk, Wv);
    k_zero_red<<<34, 256>>>();
    k_fc0<<<GB, 256, FSM>>>(x, fc0_b, ln_w, ln_b);
    k_qkv<<<QKVB, 256, QSM>>>(0, bq, bk, bv);
    k_reduce<<<320, 256>>>();
    k_pkvs<<<18, 256>>>();
    cudaStreamWaitEvent(0, evB, 0);                              // join before gather
    k_attnc<<<GB, 256>>>(ln_w + HIDD, ln_b + HIDD, fco_w, fco_b, out, 0);
    k_zero_red<<<34, 256>>>();
    k_qkv<<<QKVB, 256, QSM>>>(1, bq + HD, bk + HD, bv + HD);
    k_reduce<<<320, 256>>>();
    k_pkvs<<<18, 256>>>();
    k_attnc<<<GB, 256>>>(ln_w + 2 * HIDD, ln_b + 2 * HIDD, fco_w, fco_b, out, 1);
}

// round 16
// speedup vs baseline: 1.0995x; 1.0410x over previous
#include <cuda_runtime.h>

#define Nn    100000
#define Ee    800000
#define INF   256
#define HIDD  64
#define HD    128
#define CC    40
#define EPSL  1e-5f
#define FULL  0xffffffffu
#define GBLK  1564
#define QKVB  782
#define EMAX  2560

// ---------------- scratch ----------------
__device__ float g_vm[Nn * HIDD];
__device__ float g_rsq[Nn];
__device__ float g_kvs[2 * 8192];          // [layer][head][m][d]
__device__ float g_sumK[2 * HD];
__device__ float g_sumV[2 * HD];
__device__ float g_sums[4];                // [layer][{q2,k2}]
__device__ int   g_cnt[Nn];
__device__ int   g_ptr[Nn + 1];
__device__ int   g_cur[Nn];
__device__ int   g_erow[Ee];
__device__ int   g_blk[512];
__device__ unsigned g_hh[Nn * 32];
__device__ unsigned g_hl[Nn * 32];
__device__ unsigned g_qf[(size_t)GBLK * 4096];
__device__ unsigned g_kp[Nn * 64];
__device__ unsigned g_vp[Nn * 64];
__device__ unsigned g_kvsp[2 * 4608];
__device__ unsigned g_w0h[8192], g_w0l[8192];
__device__ unsigned g_wfh[24576], g_wfl[24576];

// ---------------- bf16 helpers ----------------
__device__ __forceinline__ unsigned packbf2(float f0, float f1) {
    unsigned r; asm("cvt.rn.bf16x2.f32 %0, %1, %2;" : "=r"(r) : "f"(f1), "f"(f0)); return r;
}
__device__ __forceinline__ void bsplit2(float f0, float f1, unsigned& h, unsigned& l) {
    h = packbf2(f0, f1);
    float h0 = __uint_as_float(h << 16);
    float h1 = __uint_as_float(h & 0xffff0000u);
    l = packbf2(f0 - h0, f1 - h1);
}
__device__ __forceinline__ float bfLO(unsigned u) { return __uint_as_float(u << 16); }
__device__ __forceinline__ float bfHI(unsigned u) { return __uint_as_float(u & 0xffff0000u); }
__device__ __forceinline__ void mma16(float* d, const unsigned* a, const unsigned* b) {
    asm volatile("mma.sync.aligned.m16n8k16.row.col.f32.bf16.bf16.f32 "
        "{%0,%1,%2,%3}, {%4,%5,%6,%7}, {%8,%9}, {%0,%1,%2,%3};"
        : "+f"(d[0]), "+f"(d[1]), "+f"(d[2]), "+f"(d[3])
        : "r"(a[0]), "r"(a[1]), "r"(a[2]), "r"(a[3]), "r"(b[0]), "r"(b[1]));
}

// frag position for A element pair: row r (0..63), pair p (0..31)
__device__ __forceinline__ int aFragPos(int r, int p) {
    return (((r >> 4) * 4 + (p >> 3)) * 32 + ((r & 7) * 4 + (p & 3))) * 4
           + ((r >> 3) & 1) + 2 * ((p >> 2) & 1);
}

// ---------------- weight pre-split ----------------
__global__ void k_prep(const float* __restrict__ fc0_w, const float* __restrict__ Wq,
                       const float* __restrict__ Wk, const float* __restrict__ Wv) {
    int id = blockIdx.x * 256 + threadIdx.x;
    if (id < 8192) {
        int kc = id >> 11, rem = id & 2047;
        int reg = rem & 1, lane = (rem >> 1) & 31, ntg = (rem >> 6) & 7, kt = rem >> 9;
        int t = lane & 3, gg = lane >> 2;
        int k = kc * 64 + kt * 16 + reg * 8 + 2 * t;
        int c = ntg * 8 + gg;
        float f0 = fc0_w[k * HIDD + c], f1 = fc0_w[(k + 1) * HIDD + c];
        unsigned h, l; bsplit2(f0, f1, h, l);
        g_w0h[id] = h; g_w0l[id] = l;
    } else if (id < 32768) {
        int id2 = id - 8192;
        int layer = id2 / 12288, r3 = id2 % 12288;
        int mat = r3 >> 12, cc2 = (r3 >> 11) & 1, rem = r3 & 2047;
        int reg = rem & 1, lane = (rem >> 1) & 31, ntg = (rem >> 6) & 7, kt = rem >> 9;
        int t = lane & 3, gg = lane >> 2;
        const float* W = (mat == 0 ? Wq : (mat == 1 ? Wk : Wv)) + (size_t)layer * HIDD * HD;
        int k = kt * 16 + reg * 8 + 2 * t;
        int cg = cc2 * 64 + ntg * 8 + gg;
        float f0 = W[k * HD + cg], f1 = W[(k + 1) * HD + cg];
        unsigned h, l; bsplit2(f0, f1, h, l);
        g_wfh[id2] = h; g_wfl[id2] = l;
    }
}

// ---------------- fc0: all-A-upfront, ONE sync, barrier-free mainloop ----------------
__global__ void k_fc0(const float* __restrict__ x, const float* __restrict__ bias,
                      const float* __restrict__ lnw, const float* __restrict__ lnb) {
    extern __shared__ __align__(16) unsigned smf[];
    float* scr = (float*)smf;
    int tid = threadIdx.x, lane = tid & 31, warp = tid >> 5;
    int rw = warp & 3, cw = warp >> 2, g = lane >> 2, t = lane & 3;
    int row0 = blockIdx.x * 64;
#pragma unroll
    for (int kc = 0; kc < 4; kc++) {
        float4 xr[4];
#pragma unroll
        for (int i = 0; i < 4; i++) {
            int idx = tid + i * 256;
            int r = idx >> 4, q4 = idx & 15;
            int gr = row0 + r;
            xr[i] = (gr < Nn) ? *(const float4*)&x[(size_t)gr * INF + kc * 64 + q4 * 4]
                              : make_float4(0.f, 0.f, 0.f, 0.f);
        }
#pragma unroll
        for (int i = 0; i < 4; i++) {
            int idx = tid + i * 256;
            int r = idx >> 4, q4 = idx & 15;
            unsigned h0, l0, h1, l1;
            bsplit2(xr[i].x, xr[i].y, h0, l0);
            bsplit2(xr[i].z, xr[i].w, h1, l1);
            int pos0 = kc * 2048 + aFragPos(r, q4 * 2);
            int pos1 = kc * 2048 + aFragPos(r, q4 * 2 + 1);
            smf[pos0] = h0; smf[8192 + pos0] = l0;
            smf[pos1] = h1; smf[8192 + pos1] = l1;
        }
    }
    __syncthreads();
    float acc[4][4] = {};
#pragma unroll
    for (int u = 0; u < 16; u++) {
        int kc = u >> 2, kt = u & 3;
        int abase = kc * 2048 + ((rw * 4 + kt) * 32 + lane) * 4;
        uint4 ah = *(const uint4*)&smf[abase];
        uint4 al = *(const uint4*)&smf[8192 + abase];
        const unsigned* wh = g_w0h + kc * 2048;
        const unsigned* wl = g_w0l + kc * 2048;
#pragma unroll
        for (int nt = 0; nt < 4; nt++) {
            int off = ((kt * 8 + cw * 4 + nt) * 32 + lane) * 2;
            uint2 bh = *(const uint2*)&wh[off];
            uint2 bl = *(const uint2*)&wl[off];
            mma16(acc[nt], (const unsigned*)&ah, (const unsigned*)&bh);
            mma16(acc[nt], (const unsigned*)&ah, (const unsigned*)&bl);
            mma16(acc[nt], (const unsigned*)&al, (const unsigned*)&bh);
        }
    }
    __syncthreads();
#pragma unroll
    for (int nt = 0; nt < 4; nt++) {
        int c0 = cw * 32 + nt * 8 + t * 2;
        float b0v = bias[c0], b1v = bias[c0 + 1];
        int r0 = rw * 16 + g, r1 = r0 + 8;
        scr[r0 * 68 + c0] = acc[nt][0] + b0v; scr[r0 * 68 + c0 + 1] = acc[nt][1] + b1v;
        scr[r1 * 68 + c0] = acc[nt][2] + b0v; scr[r1 * 68 + c0 + 1] = acc[nt][3] + b1v;
    }
    __syncthreads();
    int r = tid >> 2, sub = tid & 3;
    float vbuf[16];
    float s = 0.f, sq = 0.f;
#pragma unroll
    for (int j = 0; j < 16; j++) { float v = scr[r * 68 + sub * 16 + j]; vbuf[j] = v; s += v; sq += v * v; }
    s += __shfl_xor_sync(FULL, s, 1); sq += __shfl_xor_sync(FULL, sq, 1);
    s += __shfl_xor_sync(FULL, s, 2); sq += __shfl_xor_sync(FULL, sq, 2);
    float mu = s * 0.015625f;
    float var = sq * 0.015625f - mu * mu;
    float rs = rsqrtf(var + EPSL);
    int gr = row0 + r;
    if (gr < Nn) {
#pragma unroll
        for (int jp = 0; jp < 8; jp++) {
            int c = sub * 16 + jp * 2;
            float y0 = fmaxf((vbuf[jp * 2] - mu) * rs * lnw[c] + lnb[c], 0.f);
            float y1 = fmaxf((vbuf[jp * 2 + 1] - mu) * rs * lnw[c + 1] + lnb[c + 1], 0.f);
            unsigned h, l; bsplit2(y0, y1, h, l);
            g_hh[(size_t)gr * 32 + sub * 8 + jp] = h;
            g_hl[(size_t)gr * 32 + sub * 8 + jp] = l;
        }
    }
}

// ---------------- CSR build ----------------
__global__ void k_zcnt() { int i = blockIdx.x * 256 + threadIdx.x; if (i < Nn) g_cnt[i] = 0; }
__global__ void k_count(const int* __restrict__ col) {
    int e = blockIdx.x * 256 + threadIdx.x;
    if (e < Ee) atomicAdd(&g_cnt[col[e]], 1);
}
__global__ void k_rsqk() {
    int i = blockIdx.x * 256 + threadIdx.x;
    if (i < Nn) { int c = g_cnt[i]; g_rsq[i] = c > 0 ? rsqrtf((float)c) : 0.f; }
}
__device__ __forceinline__ int blockScanIncl(int val, int* wsum) {
    int lane = threadIdx.x & 31, wid = threadIdx.x >> 5;
#pragma unroll
    for (int o = 1; o < 32; o <<= 1) {
        int n = __shfl_up_sync(FULL, val, o);
        if (lane >= o) val += n;
    }
    if (lane == 31) wsum[wid] = val;
    __syncthreads();
    if (wid == 0) {
        int nw = blockDim.x >> 5;
        int w = (lane < nw) ? wsum[lane] : 0;
#pragma unroll
        for (int o = 1; o < 32; o <<= 1) {
            int n = __shfl_up_sync(FULL, w, o);
            if (lane >= o) w += n;
        }
        wsum[lane] = w;
    }
    __syncthreads();
    return val + (wid > 0 ? wsum[wid - 1] : 0);
}
__global__ void k_scan1() {
    __shared__ int wsum[32];
    int i = blockIdx.x * 256 + threadIdx.x;
    int v = (i < Nn) ? g_cnt[i] : 0;
    int incl = blockScanIncl(v, wsum);
    if (i < Nn) g_ptr[i] = incl - v;
    if (threadIdx.x == 255) g_blk[blockIdx.x] = incl;
}
__global__ void k_scan2() {
    __shared__ int wsum[32];
    const int NB = (Nn + 255) / 256;
    int v = (threadIdx.x < NB) ? g_blk[threadIdx.x] : 0;
    int incl = blockScanIncl(v, wsum);
    if (threadIdx.x < NB) g_blk[threadIdx.x] = incl - v;
}
__global__ void k_scan3() {
    int i = blockIdx.x * 256 + threadIdx.x;
    if (i < Nn) {
        int p = g_ptr[i] + g_blk[i >> 8];
        g_ptr[i] = p; g_cur[i] = p;
    }
    if (i == 0) g_ptr[Nn] = Ee;
}
__global__ void k_fill(const int* __restrict__ row, const int* __restrict__ col) {
    int e = blockIdx.x * 256 + threadIdx.x;
    if (e < Ee) {
        int c = col[e];
        int p = atomicAdd(&g_cur[c], 1);
        g_erow[p] = row[e];
    }
}

// ---------------- zero both layers' reduction state ----------------
__global__ void k_zero_red() {
    int i = blockIdx.x * 256 + threadIdx.x;   // 64 blocks = 16384 threads
    g_kvs[i] = 0.f;
    if (i < 2 * HD) { g_sumK[i] = 0.f; g_sumV[i] = 0.f; }
    if (i < 4) g_sums[i] = 0.f;
}

// ---------------- QKV: 128-row tiles, B from global, packed epilogues ----------------
__global__ __launch_bounds__(256, 2) void k_qkv(int layer, const float* __restrict__ bq,
                      const float* __restrict__ bk, const float* __restrict__ bv) {
    extern __shared__ __align__(16) unsigned smd[];   // AH 4096 | AL 4096 | E 4608
    unsigned* E = &smd[8192];
    float* Ef = (float*)E;
    __shared__ float sK[128], sV[128];
    int tid = threadIdx.x, lane = tid & 31, warp = tid >> 5;
    int rw = warp & 3, cw = warp >> 2, g = lane >> 2, t = lane & 3;
    int row0 = blockIdx.x * 128;
    const unsigned* wfh = g_wfh + layer * 12288;
    const unsigned* wfl = g_wfl + layer * 12288;
    if (tid < 128) { sK[tid] = 0.f; sV[tid] = 0.f; }
#pragma unroll
    for (int i = 0; i < 16; i++) {
        int idx = tid + i * 256;
        int r = idx >> 5, p = idx & 31;
        int gr = row0 + r;
        unsigned hv = 0, lv = 0;
        if (gr < Nn) { hv = g_hh[(size_t)gr * 32 + p]; lv = g_hl[(size_t)gr * 32 + p]; }
        int pos = (r >> 6) * 2048 + aFragPos(r & 63, p);
        smd[pos] = hv; smd[4096 + pos] = lv;
    }
    __syncthreads();
    bool rok[2][2];
#pragma unroll
    for (int tl = 0; tl < 2; tl++) {
        rok[tl][0] = (row0 + tl * 64 + rw * 16 + g) < Nn;
        rok[tl][1] = (row0 + tl * 64 + rw * 16 + g + 8) < Nn;
    }
    float q2 = 0.f, k2 = 0.f;
    float vk0[2][4][4];
#pragma unroll
    for (int ch = 0; ch < 6; ch++) {
        int mat = ch >> 1, cc2 = ch & 1;
        const float* B = mat == 0 ? bq : (mat == 1 ? bk : bv);
        bool split = (mat == 2);
        const unsigned* wh = wfh + ch * 2048;
        const unsigned* wl = wfl + ch * 2048;
        float acc[2][4][4] = {};
#pragma unroll
        for (int kt = 0; kt < 4; kt++) {
            uint4 ah0 = *(uint4*)&smd[((rw * 4 + kt) * 32 + lane) * 4];
            uint4 ah1 = *(uint4*)&smd[2048 + ((rw * 4 + kt) * 32 + lane) * 4];
            uint4 al0, al1;
            if (split) {
                al0 = *(uint4*)&smd[4096 + ((rw * 4 + kt) * 32 + lane) * 4];
                al1 = *(uint4*)&smd[6144 + ((rw * 4 + kt) * 32 + lane) * 4];
            }
#pragma unroll
            for (int nt = 0; nt < 4; nt++) {
                int off = ((kt * 8 + cw * 4 + nt) * 32 + lane) * 2;
                uint2 bh = *(const uint2*)&wh[off];
                mma16(acc[0][nt], (const unsigned*)&ah0, (const unsigned*)&bh);
                mma16(acc[1][nt], (const unsigned*)&ah1, (const unsigned*)&bh);
                if (split) {
                    uint2 bl = *(const uint2*)&wl[off];
                    mma16(acc[0][nt], (const unsigned*)&ah0, (const unsigned*)&bl);
                    mma16(acc[0][nt], (const unsigned*)&al0, (const unsigned*)&bh);
                    mma16(acc[1][nt], (const unsigned*)&ah1, (const unsigned*)&bl);
                    mma16(acc[1][nt], (const unsigned*)&al1, (const unsigned*)&bh);
                }
            }
        }
#pragma unroll
        for (int nt = 0; nt < 4; nt++) {
            int cgl = cc2 * 64 + cw * 32 + nt * 8 + t * 2;
            float b0v = B[cgl], b1v = B[cgl + 1];
            float c0s = 0.f, c1s = 0.f;
#pragma unroll
            for (int tl = 0; tl < 2; tl++) {
                acc[tl][nt][0] += b0v; acc[tl][nt][1] += b1v;
                acc[tl][nt][2] += b0v; acc[tl][nt][3] += b1v;
                float v00 = rok[tl][0] ? acc[tl][nt][0] : 0.f;
                float v01 = rok[tl][0] ? acc[tl][nt][1] : 0.f;
                float v10 = rok[tl][1] ? acc[tl][nt][2] : 0.f;
                float v11 = rok[tl][1] ? acc[tl][nt][3] : 0.f;
                if (mat == 0)      q2 += v00 * v00 + v01 * v01 + v10 * v10 + v11 * v11;
                else if (mat == 1) k2 += v00 * v00 + v01 * v01 + v10 * v10 + v11 * v11;
                if (mat >= 1) { c0s += v00 + v10; c1s += v01 + v11; }
            }
            if (mat >= 1) {
                c0s += __shfl_xor_sync(FULL, c0s, 4);  c1s += __shfl_xor_sync(FULL, c1s, 4);
                c0s += __shfl_xor_sync(FULL, c0s, 8);  c1s += __shfl_xor_sync(FULL, c1s, 8);
                c0s += __shfl_xor_sync(FULL, c0s, 16); c1s += __shfl_xor_sync(FULL, c1s, 16);
                if (g == 0) {
                    float* sd = (mat == 1) ? sK : sV;
                    atomicAdd(&sd[cgl], c0s);
                    atomicAdd(&sd[cgl + 1], c1s);
                }
            }
        }
        int r0 = rw * 16 + g, r1 = r0 + 8;
        if (mat == 0) {
            __syncthreads();
#pragma unroll
            for (int tl = 0; tl < 2; tl++)
#pragma unroll
                for (int nt = 0; nt < 4; nt++) {
                    int p = cw * 16 + nt * 4 + t;
                    E[tl * 2048 + aFragPos(r0, p)] = packbf2(acc[tl][nt][0], acc[tl][nt][1]);
                    E[tl * 2048 + aFragPos(r1, p)] = packbf2(acc[tl][nt][2], acc[tl][nt][3]);
                }
            __syncthreads();
#pragma unroll
            for (int i = 0; i < 4; i++) {
                int u = (tid + i * 256) * 4;
                int tile = u >> 11, w = u & 2047;
                *(uint4*)&g_qf[(size_t)(blockIdx.x * 2 + tile) * 4096 + cc2 * 2048 + w] =
                    *(uint4*)&E[u];
            }
        } else {
            unsigned* dst = (mat == 1) ? g_kp : g_vp;
#pragma unroll
            for (int tl = 0; tl < 2; tl++) {
                __syncthreads();
#pragma unroll
                for (int nt = 0; nt < 4; nt++) {
                    int p = cw * 16 + nt * 4 + t;
                    E[r0 * 36 + p] = packbf2(acc[tl][nt][0], acc[tl][nt][1]);
                    E[r1 * 36 + p] = packbf2(acc[tl][nt][2], acc[tl][nt][3]);
                }
                __syncthreads();
#pragma unroll
                for (int i = 0; i < 2; i++) {
                    int idx4 = tid + i * 256;
                    int r = idx4 >> 3, p4 = idx4 & 7;
                    int gr = row0 + tl * 64 + r;
                    if (gr < Nn)
                        *(uint4*)&dst[(size_t)gr * 64 + cc2 * 32 + p4 * 4] =
                            *(uint4*)&E[r * 36 + p4 * 4];
                }
            }
            if (mat == 2) {
                if (cc2 == 0) {
#pragma unroll
                    for (int tl = 0; tl < 2; tl++)
#pragma unroll
                        for (int nt = 0; nt < 4; nt++)
#pragma unroll
                            for (int j = 0; j < 4; j++) vk0[tl][nt][j] = acc[tl][nt][j];
                } else {
#pragma unroll
                    for (int tl = 0; tl < 2; tl++) {
                        __syncthreads();
#pragma unroll
                        for (int nt = 0; nt < 4; nt++) {
                            int c0 = cw * 32 + nt * 8 + 2 * t;
                            Ef[r0 * 72 + c0]     = 0.5f * (vk0[tl][nt][0] + acc[tl][nt][0]);
                            Ef[r0 * 72 + c0 + 1] = 0.5f * (vk0[tl][nt][1] + acc[tl][nt][1]);
                            Ef[r1 * 72 + c0]     = 0.5f * (vk0[tl][nt][2] + acc[tl][nt][2]);
                            Ef[r1 * 72 + c0 + 1] = 0.5f * (vk0[tl][nt][3] + acc[tl][nt][3]);
                        }
                        __syncthreads();
#pragma unroll
                        for (int i = 0; i < 4; i++) {
                            int idx = tid + i * 256;
                            int r = idx >> 4, c4 = idx & 15;
                            int gr = row0 + tl * 64 + r;
                            if (gr < Nn)
                                *(float4*)&g_vm[(size_t)gr * 64 + c4 * 4] =
                                    *(float4*)&Ef[r * 72 + c4 * 4];
                        }
                    }
                }
            }
        }
    }
#pragma unroll
    for (int o = 16; o > 0; o >>= 1) {
        q2 += __shfl_xor_sync(FULL, q2, o);
        k2 += __shfl_xor_sync(FULL, k2, o);
    }
    if (lane == 0) { atomicAdd(&g_sums[layer * 2], q2); atomicAdd(&g_sums[layer * 2 + 1], k2); }
    __syncthreads();
    if (tid < 128) {
        atomicAdd(&g_sumK[layer * HD + tid], sK[tid]);
        atomicAdd(&g_sumV[layer * HD + tid], sV[tid]);
    }
}

// ---------------- kvs = k^T v : packed bf16 inputs ----------------
__global__ void k_reduce(int layer) {
    __shared__ __align__(16) unsigned kraw[2048];
    __shared__ __align__(16) unsigned uraw[2048];
    __shared__ __align__(16) unsigned afr[2048];
    __shared__ __align__(16) unsigned bfr[2048];
    int tid = threadIdx.x, lane = tid & 31, warp = tid >> 5;
    int h = warp >> 2, mt = warp & 3;
    int t = lane & 3, g = lane >> 2;
    float* kvs = g_kvs + layer * 8192;
    float acc[8][4] = {};
    const int NT = Nn / 32;
    for (int tt = blockIdx.x; tt < NT; tt += gridDim.x) {
        __syncthreads();
#pragma unroll
        for (int i = 0; i < 2; i++) {
            int idx4 = tid + i * 256;
            int n = idx4 >> 4, p4 = idx4 & 15;
            *(uint4*)&kraw[n * 64 + p4 * 4] =
                *(const uint4*)&g_kp[(size_t)(tt * 32 + n) * 64 + p4 * 4];
            *(uint4*)&uraw[n * 64 + p4 * 4] =
                *(const uint4*)&g_vp[(size_t)(tt * 32 + n) * 64 + p4 * 4];
        }
        __syncthreads();
#pragma unroll
        for (int i = 0; i < 8; i++) {
            int idx = tid + i * 256;
            int j = idx & 3, ln = (idx >> 2) & 31, mtt = (idx >> 7) & 3,
                ks = (idx >> 9) & 1, hh = (idx >> 10) & 1;
            int lt = ln & 3, lg = ln >> 2;
            int m = mtt * 16 + lg + (j & 1) * 8;
            int n0 = ks * 16 + 2 * lt + (j >> 1) * 8;
            int hm = hh * 64 + m;
            unsigned u0 = kraw[n0 * 64 + (hm >> 1)];
            unsigned u1 = kraw[(n0 + 1) * 64 + (hm >> 1)];
            afr[idx] = __byte_perm(u0, u1, (hm & 1) ? 0x7632 : 0x5410);
        }
#pragma unroll
        for (int i = 0; i < 8; i++) {
            int idx = tid + i * 256;
            int reg = idx & 1, ln = (idx >> 1) & 31, ntg = (idx >> 6) & 7,
                ks = (idx >> 9) & 1, hh = (idx >> 10) & 1;
            int lt = ln & 3, lg = ln >> 2;
            int hd = hh * 64 + ntg * 8 + lg;
            int n0 = ks * 16 + 2 * lt + reg * 8;
            unsigned u0 = uraw[n0 * 64 + (hd >> 1)];
            unsigned u1 = uraw[(n0 + 1) * 64 + (hd >> 1)];
            bfr[idx] = __byte_perm(u0, u1, (hd & 1) ? 0x7632 : 0x5410);
        }
        __syncthreads();
#pragma unroll
        for (int ks = 0; ks < 2; ks++) {
            uint4 a = *(uint4*)&afr[((h * 2 + ks) * 4 + mt) * 128 + lane * 4];
#pragma unroll
            for (int nt = 0; nt < 8; nt++) {
                uint2 b = *(uint2*)&bfr[(((h * 2 + ks) * 8 + nt) * 32 + lane) * 2];
                mma16(acc[nt], (const unsigned*)&a, (const unsigned*)&b);
            }
        }
    }
#pragma unroll
    for (int nt = 0; nt < 8; nt++) {
        int c0 = nt * 8 + 2 * t;
        int r0 = mt * 16 + g, r1 = r0 + 8;
        atomicAdd(&kvs[h * 4096 + r0 * 64 + c0],     acc[nt][0]);
        atomicAdd(&kvs[h * 4096 + r0 * 64 + c0 + 1], acc[nt][1]);
        atomicAdd(&kvs[h * 4096 + r1 * 64 + c0],     acc[nt][2]);
        atomicAdd(&kvs[h * 4096 + r1 * 64 + c0 + 1], acc[nt][3]);
    }
}

// ---------------- pack kvs (+ sumK as col 64) into B-fragment order ----------------
__global__ void k_pkvs(int layer) {
    int gid = blockIdx.x * 256 + threadIdx.x;
    if (gid >= 4608) return;
    int h = gid / 2304, rem = gid % 2304;
    int reg = rem & 1, ln = (rem >> 1) & 31, ntg = (rem >> 6) % 9, kt = rem / 576;
    int lt = ln & 3, lg = ln >> 2;
    int m = kt * 16 + reg * 8 + 2 * lt;
    const float* kvs = g_kvs + layer * 8192;
    const float* sumK = g_sumK + layer * HD;
    unsigned val;
    if (ntg < 8) {
        int c = ntg * 8 + lg;
        val = packbf2(kvs[h * 4096 + m * 64 + c], kvs[h * 4096 + (m + 1) * 64 + c]);
    } else {
        val = (lg == 0) ? packbf2(sumK[h * 64 + m], sumK[h * 64 + m + 1]) : 0u;
    }
    g_kvsp[layer * 4608 + gid] = val;
}

// ---------------- fused attention + GCN gather + LN (+ optional final projection) ----------------
__global__ void k_attnc(int layer, const float* __restrict__ lnw, const float* __restrict__ lnb,
                        const float* __restrict__ fcow, const float* __restrict__ fcob,
                        float* __restrict__ out, int last) {
    __shared__ float scrf[64 * 68];
    __shared__ float sVs[128];
    __shared__ float denS[128];
    __shared__ int   sE[EMAX];
    __shared__ float sWt[EMAX];
    int tid = threadIdx.x, lane = tid & 31, warp = tid >> 5;
    int rw = warp & 3, cw = warp >> 2, g = lane >> 2, t = lane & 3;
    int row0 = blockIdx.x * 64;
    const unsigned* kvsp = g_kvsp + layer * 4608;
    int e0 = g_ptr[row0];
    int rend = (row0 + 64 < Nn) ? row0 + 64 : Nn;
    int nE = g_ptr[rend] - e0;
    bool staged = (nE <= EMAX);
    if (staged) {
        for (int i = tid; i < nE; i += 256) {
            int rr = g_erow[e0 + i];
            sE[i] = rr;
            sWt[i] = g_rsq[rr];
        }
    }
    float sc = rsqrtf(g_sums[layer * 2] * g_sums[layer * 2 + 1]);
    if (tid < 128) sVs[tid] = g_sumV[layer * HD + tid];
    float acc0[5][4] = {}, acc1[5][4] = {};
    int ntn = 4 + cw;
#pragma unroll
    for (int kt = 0; kt < 4; kt++) {
        uint4 a = *(const uint4*)&g_qf[(size_t)blockIdx.x * 4096 + ((rw * 4 + kt) * 32 + lane) * 4];
#pragma unroll
        for (int nt = 0; nt < 5; nt++) {
            if (nt < ntn) {
                int ntg = cw * 4 + nt;
                uint2 b = *(const uint2*)&kvsp[((kt * 9 + ntg) * 32 + lane) * 2];
                mma16(acc0[nt], (const unsigned*)&a, (const unsigned*)&b);
            }
        }
    }
#pragma unroll
    for (int kt = 0; kt < 4; kt++) {
        uint4 a = *(const uint4*)&g_qf[(size_t)blockIdx.x * 4096 + 2048 + ((rw * 4 + kt) * 32 + lane) * 4];
#pragma unroll
        for (int nt = 0; nt < 5; nt++) {
            if (nt < ntn) {
                int ntg = cw * 4 + nt;
                uint2 b = *(const uint2*)&kvsp[2304 + ((kt * 9 + ntg) * 32 + lane) * 2];
                mma16(acc1[nt], (const unsigned*)&a, (const unsigned*)&b);
            }
        }
    }
    if (cw == 1 && t == 0) {
        int r0 = rw * 16 + g;
        denS[r0]          = acc0[4][0] * sc + (float)Nn;
        denS[r0 + 8]      = acc0[4][2] * sc + (float)Nn;
        denS[64 + r0]     = acc1[4][0] * sc + (float)Nn;
        denS[64 + r0 + 8] = acc1[4][2] * sc + (float)Nn;
    }
    __syncthreads();
#pragma unroll
    for (int nt = 0; nt < 4; nt++) {
        int c = cw * 32 + nt * 8 + 2 * t;
        int r0 = rw * 16 + g, r1 = r0 + 8;
        float d00 = denS[r0], d01 = denS[r1];
        float d10 = denS[64 + r0], d11 = denS[64 + r1];
        scrf[r0 * 68 + c]     = 0.5f * ((acc0[nt][0] * sc + sVs[c])     / d00 + (acc1[nt][0] * sc + sVs[64 + c])     / d10);
        scrf[r0 * 68 + c + 1] = 0.5f * ((acc0[nt][1] * sc + sVs[c + 1]) / d00 + (acc1[nt][1] * sc + sVs[64 + c + 1]) / d10);
        scrf[r1 * 68 + c]     = 0.5f * ((acc0[nt][2] * sc + sVs[c])     / d01 + (acc1[nt][2] * sc + sVs[64 + c])     / d11);
        scrf[r1 * 68 + c + 1] = 0.5f * ((acc0[nt][3] * sc + sVs[c + 1]) / d01 + (acc1[nt][3] * sc + sVs[64 + c + 1]) / d11);
    }
    __syncthreads();
    int half = lane >> 4, hl = lane & 15;
#pragma unroll
    for (int pass = 0; pass < 4; pass++) {
        int nl = pass * 16 + warp * 2 + half;
        int n = row0 + nl;
        if (n < Nn) {
            int p0 = g_ptr[n], p1 = g_ptr[n + 1];
            float rn = g_rsq[n];
            float ax = 0.f, ay = 0.f, az = 0.f, aw = 0.f;
            if (staged) {
                int q = p0 - e0, q1 = p1 - e0;
                for (; q + 4 <= q1; q += 4) {
                    int r0 = sE[q], r1 = sE[q + 1], r2 = sE[q + 2], r3 = sE[q + 3];
                    float w0 = rn * sWt[q],     w1 = rn * sWt[q + 1];
                    float w2 = rn * sWt[q + 2], w3 = rn * sWt[q + 3];
                    float4 va = *(const float4*)&g_vm[(size_t)r0 * 64 + hl * 4];
                    float4 vb = *(const float4*)&g_vm[(size_t)r1 * 64 + hl * 4];
                    float4 vc = *(const float4*)&g_vm[(size_t)r2 * 64 + hl * 4];
                    float4 vd = *(const float4*)&g_vm[(size_t)r3 * 64 + hl * 4];
                    ax += w0 * va.x + w1 * vb.x + w2 * vc.x + w3 * vd.x;
                    ay += w0 * va.y + w1 * vb.y + w2 * vc.y + w3 * vd.y;
                    az += w0 * va.z + w1 * vb.z + w2 * vc.z + w3 * vd.z;
                    aw += w0 * va.w + w1 * vb.w + w2 * vc.w + w3 * vd.w;
                }
                for (; q < q1; q++) {
                    int r0 = sE[q];
                    float w0 = rn * sWt[q];
                    float4 va = *(const float4*)&g_vm[(size_t)r0 * 64 + hl * 4];
                    ax += w0 * va.x; ay += w0 * va.y; az += w0 * va.z; aw += w0 * va.w;
                }
            } else {
                for (int e = p0; e < p1; e++) {
                    int r0 = g_erow[e];
                    float w0 = rn * g_rsq[r0];
                    float4 va = *(const float4*)&g_vm[(size_t)r0 * 64 + hl * 4];
                    ax += w0 * va.x; ay += w0 * va.y; az += w0 * va.z; aw += w0 * va.w;
                }
            }
            float4 ov = *(const float4*)&scrf[nl * 68 + hl * 4];
            // reconstruct prev from split-bf16 (hi+lo), rel err ~4e-6
            uint2 uh = *(const uint2*)&g_hh[(size_t)n * 32 + hl * 2];
            uint2 ul = *(const uint2*)&g_hl[(size_t)n * 32 + hl * 2];
            float4 pv;
            pv.x = bfLO(uh.x) + bfLO(ul.x);
            pv.y = bfHI(uh.x) + bfHI(ul.x);
            pv.z = bfLO(uh.y) + bfLO(ul.y);
            pv.w = bfHI(uh.y) + bfHI(ul.y);
            float4 hv;
            hv.x = 0.5f * (ov.x + ax) + 0.5f * pv.x;
            hv.y = 0.5f * (ov.y + ay) + 0.5f * pv.y;
            hv.z = 0.5f * (ov.z + az) + 0.5f * pv.z;
            hv.w = 0.5f * (ov.w + aw) + 0.5f * pv.w;
            float s = hv.x + hv.y + hv.z + hv.w;
            float sq = hv.x * hv.x + hv.y * hv.y + hv.z * hv.z + hv.w * hv.w;
#pragma unroll
            for (int o = 1; o < 16; o <<= 1) {
                s += __shfl_xor_sync(FULL, s, o);
                sq += __shfl_xor_sync(FULL, sq, o);
            }
            float mu = s * 0.015625f;
            float var = sq * 0.015625f - mu * mu;
            float rs = rsqrtf(var + EPSL);
            float4 lw = *(const float4*)&lnw[hl * 4];
            float4 lb = *(const float4*)&lnb[hl * 4];
            float4 y;
            y.x = (hv.x - mu) * rs * lw.x + lb.x;
            y.y = (hv.y - mu) * rs * lw.y + lb.y;
            y.z = (hv.z - mu) * rs * lw.z + lb.z;
            y.w = (hv.w - mu) * rs * lw.w + lb.w;
            if (last) {
                *(float4*)&scrf[nl * 68 + hl * 4] = y;
            } else {
                unsigned h0, l0, h1, l1;
                bsplit2(y.x, y.y, h0, l0);
                bsplit2(y.z, y.w, h1, l1);
                *(uint2*)&g_hh[(size_t)n * 32 + hl * 2] = make_uint2(h0, h1);
                *(uint2*)&g_hl[(size_t)n * 32 + hl * 2] = make_uint2(l0, l1);
            }
        }
    }
    if (last) {
        __syncthreads();
        float* wsm = (float*)sE;   // 2560 floats = 64x40
        for (int i = tid; i < 2560; i += 256) wsm[i] = fcow[i];
        __syncthreads();
        int r = tid & 63, cg = tid >> 6;
        float acc[10] = {};
#pragma unroll
        for (int kk = 0; kk < 64; kk++) {
            float a = scrf[r * 68 + kk];
            const float* wr = &wsm[kk * 40 + cg * 10];
#pragma unroll
            for (int j = 0; j < 10; j++) acc[j] += a * wr[j];
        }
        int gr = row0 + r;
        if (gr < Nn) {
#pragma unroll
            for (int j = 0; j < 10; j++)
                out[(size_t)gr * CC + cg * 10 + j] = acc[j] + fcob[cg * 10 + j];
        }
    }
}

// ---------------- launcher: CSR + zeroing forked onto a side stream ----------------
extern "C" void kernel_launch(void* const* d_in, const int* in_sizes, int n_in,
                              void* d_out, int out_size) {
    (void)in_sizes; (void)n_in; (void)out_size;
    const float* x     = (const float*)d_in[0];
    const int*   ei    = (const int*)d_in[1];
    const float* fc0_w = (const float*)d_in[2];
    const float* fc0_b = (const float*)d_in[3];
    const float* ln_w  = (const float*)d_in[4];
    const float* ln_b  = (const float*)d_in[5];
    const float* Wq    = (const float*)d_in[6];
    const float* Wk    = (const float*)d_in[7];
    const float* Wv    = (const float*)d_in[8];
    const float* bq    = (const float*)d_in[9];
    const float* bk    = (const float*)d_in[10];
    const float* bv    = (const float*)d_in[11];
    const float* fco_w = (const float*)d_in[12];
    const float* fco_b = (const float*)d_in[13];
    float* out = (float*)d_out;

    const int GB = 1563;
    const int NB = (Nn + 255) / 256;
    const int EB = (Ee + 255) / 256;
    const int QSM = 51200;
    const int FSM = 65536;

    cudaFuncSetAttribute(k_qkv, cudaFuncAttributeMaxDynamicSharedMemorySize, QSM);
    cudaFuncSetAttribute(k_fc0, cudaFuncAttributeMaxDynamicSharedMemorySize, FSM);

    cudaStream_t s2;
    cudaStreamCreateWithFlags(&s2, cudaStreamNonBlocking);
    cudaEvent_t evA, evB, evZ;
    cudaEventCreateWithFlags(&evA, cudaEventDisableTiming);
    cudaEventCreateWithFlags(&evB, cudaEventDisableTiming);
    cudaEventCreateWithFlags(&evZ, cudaEventDisableTiming);

    // fork: zeroing + CSR build run concurrently with fc0 chain
    cudaEventRecord(evA, 0);
    cudaStreamWaitEvent(s2, evA, 0);
    k_zero_red<<<64, 256, 0, s2>>>();
    cudaEventRecord(evZ, s2);
    k_zcnt<<<NB, 256, 0, s2>>>();
    k_count<<<EB, 256, 0, s2>>>(ei + Ee);
    k_rsqk<<<NB, 256, 0, s2>>>();
    k_scan1<<<NB, 256, 0, s2>>>();
    k_scan2<<<1, 512, 0, s2>>>();
    k_scan3<<<NB, 256, 0, s2>>>();
    k_fill<<<EB, 256, 0, s2>>>(ei, ei + Ee);
    cudaEventRecord(evB, s2);

    // main chain (default stream)
    k_prep<<<128, 256>>>(fc0_w, Wq, Wk, Wv);
    k_fc0<<<GB, 256, FSM>>>(x, fc0_b, ln_w, ln_b);
    cudaStreamWaitEvent(0, evZ, 0);                              // sums zeroed
    k_qkv<<<QKVB, 256, QSM>>>(0, bq, bk, bv);
    k_reduce<<<320, 256>>>(0);
    k_pkvs<<<18, 256>>>(0);
    cudaStreamWaitEvent(0, evB, 0);                              // CSR ready
    k_attnc<<<GB, 256>>>(0, ln_w + HIDD, ln_b + HIDD, fco_w, fco_b, out, 0);
    k_qkv<<<QKVB, 256, QSM>>>(1, bq + HD, bk + HD, bv + HD);
    k_reduce<<<320, 256>>>(1);
    k_pkvs<<<18, 256>>>(1);
    k_attnc<<<GB, 256>>>(1, ln_w + 2 * HIDD, ln_b + 2 * HIDD, fco_w, fco_b, out, 1);
}